// round 3
// baseline (speedup 1.0000x reference)
#include <cuda_runtime.h>
#include <math.h>

// Problem constants
#define N_ 128
#define K_ 64
#define C_ 64
#define ROWS_ (N_ * K_)   // 8192

typedef unsigned long long ull;

// Scratch (device globals: no allocation allowed)
__device__ float g_U [ROWS_ * C_];   // um * ug
__device__ float g_A [ROWS_ * C_];   // h @ Wb1[:C]  + bb1
__device__ float g_B [ROWS_ * C_];   // h @ Wb1[C:]
__device__ float g_Ag[ROWS_ * C_];   // h @ Wbg1[:C] + bbg1
__device__ float g_Bg[ROWS_ * C_];   // h @ Wbg1[C:]

__device__ __forceinline__ float fast_tanh(float x) {
    return 1.0f - __fdividef(2.0f, __expf(2.0f * x) + 1.0f);
}
__device__ __forceinline__ float fast_sigmoid(float x) {
    return __fdividef(1.0f, 1.0f + __expf(-x));
}

// packed fp32 FMA (Blackwell f32x2) — 2 FMAs per issue slot
__device__ __forceinline__ ull ffma2(ull a, ull b, ull c) {
    ull d;
    asm("fma.rn.f32x2 %0, %1, %2, %3;" : "=l"(d) : "l"(a), "l"(b), "l"(c));
    return d;
}
__device__ __forceinline__ void unpack2(ull v, float& lo, float& hi) {
    asm("mov.b64 {%0, %1}, %2;" : "=f"(lo), "=f"(hi) : "l"(v));
}

// ---------------------------------------------------------------------------
// Kernel 1 (unchanged): h, unary path U, binary first-layer factors A/B/Ag/Bg
// ---------------------------------------------------------------------------
#define PREP_SMEM_FLOATS (9 * 4096 + 3 * 256)

__global__ __launch_bounds__(256)
void prep_kernel(const float* __restrict__ x,
                 const float* __restrict__ Wlin, const float* __restrict__ blin,
                 const float* __restrict__ Wu1,  const float* __restrict__ bu1,
                 const float* __restrict__ Wu2,  const float* __restrict__ bu2,
                 const float* __restrict__ Wug1, const float* __restrict__ bug1,
                 const float* __restrict__ Wug2, const float* __restrict__ bug2,
                 const float* __restrict__ Wb1,  const float* __restrict__ bb1,
                 const float* __restrict__ Wbg1, const float* __restrict__ bbg1)
{
    extern __shared__ float sm[];
    float* sWlin  = sm;
    float* sWu1   = sm + 4096;
    float* sWu2   = sm + 2 * 4096;
    float* sWug1  = sm + 3 * 4096;
    float* sWug2  = sm + 4 * 4096;
    float* sWb1a  = sm + 5 * 4096;
    float* sWb1b  = sm + 6 * 4096;
    float* sWbg1a = sm + 7 * 4096;
    float* sWbg1b = sm + 8 * 4096;
    float* sx     = sm + 9 * 4096;         // [4][64]
    float* sh     = sx + 256;              // [4][64]
    float* st     = sh + 256;              // [4][64]

    const int tid = threadIdx.x;
    for (int i = tid; i < 4096; i += 256) {
        sWlin[i]  = Wlin[i];
        sWu1[i]   = Wu1[i];
        sWu2[i]   = Wu2[i];
        sWug1[i]  = Wug1[i];
        sWug2[i]  = Wug2[i];
        sWb1a[i]  = Wb1[i];
        sWb1b[i]  = Wb1[4096 + i];
        sWbg1a[i] = Wbg1[i];
        sWbg1b[i] = Wbg1[4096 + i];
    }
    __syncthreads();

    const int rr = tid >> 6;
    const int c  = tid & 63;
    const int row0 = blockIdx.x * 64;

    for (int g = 0; g < 16; g++) {
        const int row = row0 + g * 4 + rr;
        sx[rr * 64 + c] = x[row * 64 + c];
        __syncthreads();

        float acc = blin[c];
        #pragma unroll 16
        for (int k = 0; k < 64; k++)
            acc = fmaf(sx[rr * 64 + k], sWlin[k * 64 + c], acc);
        sh[rr * 64 + c] = acc;
        __syncthreads();

        acc = bu1[c];
        #pragma unroll 16
        for (int k = 0; k < 64; k++)
            acc = fmaf(sh[rr * 64 + k], sWu1[k * 64 + c], acc);
        st[rr * 64 + c] = fast_tanh(acc);
        __syncthreads();

        float um = bu2[c];
        #pragma unroll 16
        for (int k = 0; k < 64; k++)
            um = fmaf(st[rr * 64 + k], sWu2[k * 64 + c], um);
        __syncthreads();

        acc = bug1[c];
        #pragma unroll 16
        for (int k = 0; k < 64; k++)
            acc = fmaf(sh[rr * 64 + k], sWug1[k * 64 + c], acc);
        st[rr * 64 + c] = fast_tanh(acc);
        __syncthreads();

        float ug = bug2[c];
        #pragma unroll 16
        for (int k = 0; k < 64; k++)
            ug = fmaf(st[rr * 64 + k], sWug2[k * 64 + c], ug);
        ug = fast_sigmoid(ug);

        g_U[row * 64 + c] = um * ug;

        float a  = bb1[c];
        float b  = 0.0f;
        float ag = bbg1[c];
        float bg = 0.0f;
        #pragma unroll 16
        for (int k = 0; k < 64; k++) {
            const float hv = sh[rr * 64 + k];
            a  = fmaf(hv, sWb1a [k * 64 + c], a);
            b  = fmaf(hv, sWb1b [k * 64 + c], b);
            ag = fmaf(hv, sWbg1a[k * 64 + c], ag);
            bg = fmaf(hv, sWbg1b[k * 64 + c], bg);
        }
        g_A [row * 64 + c] = a;
        g_B [row * 64 + c] = b;
        g_Ag[row * 64 + c] = ag;
        g_Bg[row * 64 + c] = bg;
        __syncthreads();
    }
}

// ---------------------------------------------------------------------------
// Kernel 2: one block per (n, group of 4 j's). 2048 blocks, 256 threads.
// Phase 1: T2[k][2i..2i+1] = dup(tanh(A[n,j][k] + B[n,i][k])) (pairs for f32x2)
//          B read straight from global (L2-resident), smem freed for T-dup.
// Phase 2: two 64x64x64 GEMMs with packed f32x2 FMAs, 4i x 4c per thread.
// Phase 3: gate + i-reduction.
// ---------------------------------------------------------------------------
#define TPAD2 140   // floats per duplicated-T row (conflict-free STS.128)
#define MAIN_SMEM_FLOATS (2 * 4096 + 2 * 64 * TPAD2 + 2 * 256 + 16 * 64)

__global__ __launch_bounds__(256, 2)
void main_kernel(const float* __restrict__ Wb2,  const float* __restrict__ bb2,
                 const float* __restrict__ Wbg2, const float* __restrict__ bbg2,
                 float* __restrict__ out)
{
    extern __shared__ float sm[];
    float* sW2  = sm;                        // [64][64]
    float* sWg2 = sm + 4096;                 // [64][64]
    float* sT2  = sm + 2 * 4096;             // [64][TPAD2] duplicated pairs
    float* sTg2 = sT2 + 64 * TPAD2;          // [64][TPAD2]
    float* sA   = sTg2 + 64 * TPAD2;         // [4][64]
    float* sAg  = sA + 256;                  // [4][64]
    float* sred = sAg + 256;                 // [16][64]

    const int tid = threadIdx.x;
    const int n   = blockIdx.x >> 4;
    const int jg  = blockIdx.x & 15;

    for (int i = tid; i < 4096; i += 256) {
        sW2 [i] = Wb2[i];
        sWg2[i] = Wbg2[i];
    }
    sA [tid] = g_A [n * 4096 + jg * 256 + tid];
    sAg[tid] = g_Ag[n * 4096 + jg * 256 + tid];
    __syncthreads();

    const int ti = tid >> 4;     // 0..15 -> i-tile (4 rows)
    const int tc = tid & 15;     // 0..15 -> c-tile (4 cols)
    const int kk = tid & 63;     // phase-1: channel k
    const int qb = tid >> 6;     // phase-1: base quad 0..3

    const float* Bn  = g_B  + n * 4096;
    const float* Bgn = g_Bg + n * 4096;

    float bb2r[4], bbg2r[4];
    #pragma unroll
    for (int s = 0; s < 4; s++) {
        bb2r [s] = bb2 [4 * tc + s];
        bbg2r[s] = bbg2[4 * tc + s];
    }

    for (int jj = 0; jj < 4; jj++) {
        // ---- phase 1: build duplicated T, Tg: sT2[k][2i],[2i+1] = tanh ----
        const float aj  = sA [jj * 64 + kk];
        const float agj = sAg[jj * 64 + kk];
        #pragma unroll
        for (int m = 0; m < 4; m++) {
            const int q  = qb * 4 + m;     // i-quad 0..15
            const int i0 = 4 * q;
            float tb[4], tg[4];
            #pragma unroll
            for (int u = 0; u < 4; u++) {
                tb[u] = fast_tanh(aj  + Bn [(i0 + u) * 64 + kk]);
                tg[u] = fast_tanh(agj + Bgn[(i0 + u) * 64 + kk]);
            }
            float4* pb = (float4*)(sT2  + kk * TPAD2 + 8 * q);
            float4* pg = (float4*)(sTg2 + kk * TPAD2 + 8 * q);
            pb[0] = make_float4(tb[0], tb[0], tb[1], tb[1]);
            pb[1] = make_float4(tb[2], tb[2], tb[3], tb[3]);
            pg[0] = make_float4(tg[0], tg[0], tg[1], tg[1]);
            pg[1] = make_float4(tg[2], tg[2], tg[3], tg[3]);
        }
        __syncthreads();

        // ---- phase 2: packed-f32x2 GEMM pair, 4x4 per thread ----
        ull accb[4][2];
        ull accg[4][2];
        #pragma unroll
        for (int r = 0; r < 4; r++)
            #pragma unroll
            for (int p = 0; p < 2; p++) { accb[r][p] = 0ULL; accg[r][p] = 0ULL; }

        #pragma unroll 8
        for (int k = 0; k < 64; k++) {
            // T dup pairs: (t0,t0,t1,t1) / (t2,t2,t3,t3)
            const ulonglong2 tbl = *(const ulonglong2*)(sT2  + k * TPAD2 + 8 * ti);
            const ulonglong2 tbh = *(const ulonglong2*)(sT2  + k * TPAD2 + 8 * ti + 4);
            const ulonglong2 tgl = *(const ulonglong2*)(sTg2 + k * TPAD2 + 8 * ti);
            const ulonglong2 tgh = *(const ulonglong2*)(sTg2 + k * TPAD2 + 8 * ti + 4);
            // W natural pairs: (w0,w1) (w2,w3)
            const ulonglong2 wb  = *(const ulonglong2*)(sW2  + k * 64 + 4 * tc);
            const ulonglong2 wg  = *(const ulonglong2*)(sWg2 + k * 64 + 4 * tc);

            const ull tb_[4] = {tbl.x, tbl.y, tbh.x, tbh.y};
            const ull tg_[4] = {tgl.x, tgl.y, tgh.x, tgh.y};
            const ull wb_[2] = {wb.x, wb.y};
            const ull wg_[2] = {wg.x, wg.y};

            #pragma unroll
            for (int r = 0; r < 4; r++) {
                #pragma unroll
                for (int p = 0; p < 2; p++) {
                    accb[r][p] = ffma2(tb_[r], wb_[p], accb[r][p]);
                    accg[r][p] = ffma2(tg_[r], wg_[p], accg[r][p]);
                }
            }
        }

        // ---- phase 3: gate + partial i-reduction ----
        float mb[4][4], mg[4][4];
        #pragma unroll
        for (int r = 0; r < 4; r++) {
            #pragma unroll
            for (int p = 0; p < 2; p++) {
                unpack2(accb[r][p], mb[r][2 * p], mb[r][2 * p + 1]);
                unpack2(accg[r][p], mg[r][2 * p], mg[r][2 * p + 1]);
            }
        }
        #pragma unroll
        for (int s = 0; s < 4; s++) {
            float pr = 0.0f;
            #pragma unroll
            for (int r = 0; r < 4; r++) {
                const float gate = fast_sigmoid(mg[r][s] + bbg2r[s]);
                pr = fmaf(mb[r][s] + bb2r[s], gate, pr);
            }
            sred[ti * 64 + 4 * tc + s] = pr;
        }
        __syncthreads();

        if (tid < 64) {
            float sum = 0.0f;
            #pragma unroll
            for (int u = 0; u < 16; u++) sum += sred[u * 64 + tid];
            const int j = jg * 4 + jj;
            const int o = (n * 64 + j) * 64 + tid;
            out[o] = g_U[o] + sum * (1.0f / 63.0f);
        }
        __syncthreads();
    }
}

// ---------------------------------------------------------------------------
// launch
// ---------------------------------------------------------------------------
extern "C" void kernel_launch(void* const* d_in, const int* in_sizes, int n_in,
                              void* d_out, int out_size)
{
    const float* x    = (const float*)d_in[0];
    const float* Wlin = (const float*)d_in[1];
    const float* blin = (const float*)d_in[2];
    const float* Wu1  = (const float*)d_in[3];
    const float* bu1  = (const float*)d_in[4];
    const float* Wu2  = (const float*)d_in[5];
    const float* bu2  = (const float*)d_in[6];
    const float* Wug1 = (const float*)d_in[7];
    const float* bug1 = (const float*)d_in[8];
    const float* Wug2 = (const float*)d_in[9];
    const float* bug2 = (const float*)d_in[10];
    const float* Wb1  = (const float*)d_in[11];
    const float* bb1  = (const float*)d_in[12];
    const float* Wb2  = (const float*)d_in[13];
    const float* bb2  = (const float*)d_in[14];
    const float* Wbg1 = (const float*)d_in[15];
    const float* bbg1 = (const float*)d_in[16];
    const float* Wbg2 = (const float*)d_in[17];
    const float* bbg2 = (const float*)d_in[18];

    float* out = (float*)d_out;

    const int prep_smem = PREP_SMEM_FLOATS * (int)sizeof(float);
    const int main_smem = MAIN_SMEM_FLOATS * (int)sizeof(float);   // 110592 B
    cudaFuncSetAttribute(prep_kernel, cudaFuncAttributeMaxDynamicSharedMemorySize, prep_smem);
    cudaFuncSetAttribute(main_kernel, cudaFuncAttributeMaxDynamicSharedMemorySize, main_smem);

    prep_kernel<<<128, 256, prep_smem>>>(x, Wlin, blin, Wu1, bu1, Wu2, bu2,
                                         Wug1, bug1, Wug2, bug2,
                                         Wb1, bb1, Wbg1, bbg1);
    main_kernel<<<2048, 256, main_smem>>>(Wb2, bb2, Wbg2, bbg2, out);
}

// round 5
// speedup vs baseline: 1.4861x; 1.4861x over previous
#include <cuda_runtime.h>
#include <cuda_bf16.h>
#include <math.h>
#include <cstdint>

// Problem constants
#define N_ 128
#define K_ 64
#define C_ 64
#define ROWS_ (N_ * K_)   // 8192

// Scratch (device globals: no allocation allowed)
__device__ float g_U [ROWS_ * C_];   // um * ug
__device__ float g_A [ROWS_ * C_];   // h @ Wb1[:C]  + bb1
__device__ float g_B [ROWS_ * C_];   // h @ Wb1[C:]
__device__ float g_Ag[ROWS_ * C_];   // h @ Wbg1[:C] + bbg1
__device__ float g_Bg[ROWS_ * C_];   // h @ Wbg1[C:]

__device__ __forceinline__ float fast_tanh(float x) {
    return 1.0f - __fdividef(2.0f, __expf(2.0f * x) + 1.0f);
}
__device__ __forceinline__ float fast_sigmoid(float x) {
    return __fdividef(1.0f, 1.0f + __expf(-x));
}

// pack two fp32 into bf16x2 (first arg -> low 16 bits)
__device__ __forceinline__ uint32_t pack_bf16x2(float lo, float hi) {
    uint32_t r;
    asm("cvt.rn.bf16x2.f32 %0, %1, %2;" : "=r"(r) : "f"(hi), "f"(lo));
    return r;
}

__device__ __forceinline__ uint32_t smem_to_u32(const void* p) {
    uint32_t a;
    asm("{ .reg .u64 t; cvta.to.shared.u64 t, %1; cvt.u32.u64 %0, t; }"
        : "=r"(a) : "l"(p));
    return a;
}

// warp-level bf16 HMMA, m16n8k16, row.col, f32 accumulate (base-target PTX)
__device__ __forceinline__ void mma16816(float acc[4], const uint32_t a[4],
                                         uint32_t b0, uint32_t b1) {
    asm volatile(
        "mma.sync.aligned.m16n8k16.row.col.f32.bf16.bf16.f32 "
        "{%0,%1,%2,%3}, {%4,%5,%6,%7}, {%8,%9}, {%0,%1,%2,%3};"
        : "+f"(acc[0]), "+f"(acc[1]), "+f"(acc[2]), "+f"(acc[3])
        : "r"(a[0]), "r"(a[1]), "r"(a[2]), "r"(a[3]), "r"(b0), "r"(b1));
}

__device__ __forceinline__ void ldm_x4(uint32_t r[4], uint32_t addr) {
    asm volatile(
        "ldmatrix.sync.aligned.m8n8.x4.shared.b16 {%0,%1,%2,%3}, [%4];"
        : "=r"(r[0]), "=r"(r[1]), "=r"(r[2]), "=r"(r[3]) : "r"(addr));
}

// ---------------------------------------------------------------------------
// Kernel 1 (unchanged from R2): h, unary path U, binary factors A/B/Ag/Bg
// ---------------------------------------------------------------------------
#define PREP_SMEM_FLOATS (9 * 4096 + 3 * 256)

__global__ __launch_bounds__(256)
void prep_kernel(const float* __restrict__ x,
                 const float* __restrict__ Wlin, const float* __restrict__ blin,
                 const float* __restrict__ Wu1,  const float* __restrict__ bu1,
                 const float* __restrict__ Wu2,  const float* __restrict__ bu2,
                 const float* __restrict__ Wug1, const float* __restrict__ bug1,
                 const float* __restrict__ Wug2, const float* __restrict__ bug2,
                 const float* __restrict__ Wb1,  const float* __restrict__ bb1,
                 const float* __restrict__ Wbg1, const float* __restrict__ bbg1)
{
    extern __shared__ float sm[];
    float* sWlin  = sm;
    float* sWu1   = sm + 4096;
    float* sWu2   = sm + 2 * 4096;
    float* sWug1  = sm + 3 * 4096;
    float* sWug2  = sm + 4 * 4096;
    float* sWb1a  = sm + 5 * 4096;
    float* sWb1b  = sm + 6 * 4096;
    float* sWbg1a = sm + 7 * 4096;
    float* sWbg1b = sm + 8 * 4096;
    float* sx     = sm + 9 * 4096;
    float* sh     = sx + 256;
    float* st     = sh + 256;

    const int tid = threadIdx.x;
    for (int i = tid; i < 4096; i += 256) {
        sWlin[i]  = Wlin[i];
        sWu1[i]   = Wu1[i];
        sWu2[i]   = Wu2[i];
        sWug1[i]  = Wug1[i];
        sWug2[i]  = Wug2[i];
        sWb1a[i]  = Wb1[i];
        sWb1b[i]  = Wb1[4096 + i];
        sWbg1a[i] = Wbg1[i];
        sWbg1b[i] = Wbg1[4096 + i];
    }
    __syncthreads();

    const int rr = tid >> 6;
    const int c  = tid & 63;
    const int row0 = blockIdx.x * 64;

    for (int g = 0; g < 16; g++) {
        const int row = row0 + g * 4 + rr;
        sx[rr * 64 + c] = x[row * 64 + c];
        __syncthreads();

        float acc = blin[c];
        #pragma unroll 16
        for (int k = 0; k < 64; k++)
            acc = fmaf(sx[rr * 64 + k], sWlin[k * 64 + c], acc);
        sh[rr * 64 + c] = acc;
        __syncthreads();

        acc = bu1[c];
        #pragma unroll 16
        for (int k = 0; k < 64; k++)
            acc = fmaf(sh[rr * 64 + k], sWu1[k * 64 + c], acc);
        st[rr * 64 + c] = fast_tanh(acc);
        __syncthreads();

        float um = bu2[c];
        #pragma unroll 16
        for (int k = 0; k < 64; k++)
            um = fmaf(st[rr * 64 + k], sWu2[k * 64 + c], um);
        __syncthreads();

        acc = bug1[c];
        #pragma unroll 16
        for (int k = 0; k < 64; k++)
            acc = fmaf(sh[rr * 64 + k], sWug1[k * 64 + c], acc);
        st[rr * 64 + c] = fast_tanh(acc);
        __syncthreads();

        float ug = bug2[c];
        #pragma unroll 16
        for (int k = 0; k < 64; k++)
            ug = fmaf(st[rr * 64 + k], sWug2[k * 64 + c], ug);
        ug = fast_sigmoid(ug);

        g_U[row * 64 + c] = um * ug;

        float a  = bb1[c];
        float b  = 0.0f;
        float ag = bbg1[c];
        float bg = 0.0f;
        #pragma unroll 16
        for (int k = 0; k < 64; k++) {
            const float hv = sh[rr * 64 + k];
            a  = fmaf(hv, sWb1a [k * 64 + c], a);
            b  = fmaf(hv, sWb1b [k * 64 + c], b);
            ag = fmaf(hv, sWbg1a[k * 64 + c], ag);
            bg = fmaf(hv, sWbg1b[k * 64 + c], bg);
        }
        g_A [row * 64 + c] = a;
        g_B [row * 64 + c] = b;
        g_Ag[row * 64 + c] = ag;
        g_Bg[row * 64 + c] = bg;
        __syncthreads();
    }
}

// ---------------------------------------------------------------------------
// Kernel 2 (mma.sync bf16 hi/lo split): one block per (n, 8 j's) = 4 tiles of
// 2 j's. Per tile: A[m][k] = tanh(A_j(m)[k] + B_i(m)[k]) with m = jj*64+i,
// M=128, N=64, K=64; D = A @ W^T via 3-pass bf16 split; both paths; gate;
// reduce over i.
// ---------------------------------------------------------------------------
// byte offsets within dynamic smem
#define WPITCH_B  144                      // 72 bf16 per row
#define OFF_WB_HI 0
#define OFF_WB_LO 9216
#define OFF_WG_HI 18432
#define OFF_WG_LO 27648
#define OFF_AB_HI 36864
#define OFF_AB_LO 55296
#define OFF_AG_HI 73728
#define OFF_AG_LO 92160
#define OFF_BB2   110592
#define OFF_BBG2  110848
#define MAIN_SMEM_BYTES 111104
#define OFF_SRED  36864                    // aliases A tiles (dead after MMA)
#define SRED_PITCH 68                      // floats

__global__ __launch_bounds__(256, 2)
void main_kernel(const float* __restrict__ Wb2,  const float* __restrict__ bb2,
                 const float* __restrict__ Wbg2, const float* __restrict__ bbg2,
                 float* __restrict__ out)
{
    extern __shared__ char smem[];
    const uint32_t sb = smem_to_u32(smem);
    const int tid  = threadIdx.x;
    const int wid  = tid >> 5;
    const int lane = tid & 31;
    const int gid  = lane >> 2;
    const int tig  = lane & 3;
    const int n    = blockIdx.x >> 3;
    const int jg   = blockIdx.x & 7;

    // --- one-time: W^T bf16 hi/lo for both paths; biases ---
    for (int idx = tid; idx < 4096; idx += 256) {
        const int k = idx >> 6, c = idx & 63;
        const int off = c * WPITCH_B + k * 2;
        {
            const float w = Wb2[idx];
            const __nv_bfloat16 h = __float2bfloat16(w);
            const __nv_bfloat16 l = __float2bfloat16(w - __bfloat162float(h));
            *(__nv_bfloat16*)(smem + OFF_WB_HI + off) = h;
            *(__nv_bfloat16*)(smem + OFF_WB_LO + off) = l;
        }
        {
            const float w = Wbg2[idx];
            const __nv_bfloat16 h = __float2bfloat16(w);
            const __nv_bfloat16 l = __float2bfloat16(w - __bfloat162float(h));
            *(__nv_bfloat16*)(smem + OFF_WG_HI + off) = h;
            *(__nv_bfloat16*)(smem + OFF_WG_LO + off) = l;
        }
    }
    float* sbb2  = (float*)(smem + OFF_BB2);
    float* sbbg2 = (float*)(smem + OFF_BBG2);
    if (tid < 64) { sbb2[tid] = bb2[tid]; sbbg2[tid] = bbg2[tid]; }
    __syncthreads();

    // phase-1 mapping: thread -> (m, k-half)
    const int m   = tid >> 1;          // 0..127
    const int kh  = (tid & 1) * 32;    // 0 / 32
    const int jj1 = m >> 6;            // 0/1
    const int i1  = m & 63;

    // mma mapping
    const int m0 = wid * 16;
    const uint32_t aoff = (uint32_t)((m0 + (lane & 15)) * WPITCH_B + ((lane >> 4) * 16));

    float* sredf = (float*)(smem + OFF_SRED);

    for (int t = 0; t < 4; t++) {
        const int j0 = jg * 8 + 2 * t;

        // ---- phase 1: build bf16 hi/lo A tiles for both paths ----
        #pragma unroll
        for (int p = 0; p < 2; p++) {
            const int j = j0 + jj1;
            const float* Arow = (p ? g_Ag : g_A) + (n * 64 + j)  * 64 + kh;
            const float* Brow = (p ? g_Bg : g_B) + (n * 64 + i1) * 64 + kh;
            char* hiB = smem + (p ? OFF_AG_HI : OFF_AB_HI);
            char* loB = hiB + 18432;
            const int base = m * WPITCH_B + kh * 2;
            #pragma unroll
            for (int q = 0; q < 4; q++) {
                const float4 a0 = *(const float4*)(Arow + 8 * q);
                const float4 a1 = *(const float4*)(Arow + 8 * q + 4);
                const float4 b0 = *(const float4*)(Brow + 8 * q);
                const float4 b1 = *(const float4*)(Brow + 8 * q + 4);
                float tv[8];
                tv[0] = fast_tanh(a0.x + b0.x);
                tv[1] = fast_tanh(a0.y + b0.y);
                tv[2] = fast_tanh(a0.z + b0.z);
                tv[3] = fast_tanh(a0.w + b0.w);
                tv[4] = fast_tanh(a1.x + b1.x);
                tv[5] = fast_tanh(a1.y + b1.y);
                tv[6] = fast_tanh(a1.z + b1.z);
                tv[7] = fast_tanh(a1.w + b1.w);
                uint4 hv, lv;
                uint32_t ph, plo;
                #define SPLIT_PAIR(e0, e1, dst_h, dst_l)                       \
                    ph = pack_bf16x2(tv[e0], tv[e1]);                          \
                    {                                                          \
                        const float hf0 = __uint_as_float(ph << 16);           \
                        const float hf1 = __uint_as_float(ph & 0xFFFF0000u);   \
                        plo = pack_bf16x2(tv[e0] - hf0, tv[e1] - hf1);         \
                    }                                                          \
                    dst_h = ph; dst_l = plo;
                SPLIT_PAIR(0, 1, hv.x, lv.x)
                SPLIT_PAIR(2, 3, hv.y, lv.y)
                SPLIT_PAIR(4, 5, hv.z, lv.z)
                SPLIT_PAIR(6, 7, hv.w, lv.w)
                #undef SPLIT_PAIR
                *(uint4*)(hiB + base + 16 * q) = hv;
                *(uint4*)(loB + base + 16 * q) = lv;
            }
        }
        __syncthreads();

        // ---- MMA: per warp, 16-row strip x full N=64, both paths ----
        float accb[8][4], accg[8][4];
        #pragma unroll
        for (int nt = 0; nt < 8; nt++)
            #pragma unroll
            for (int r = 0; r < 4; r++) { accb[nt][r] = 0.f; accg[nt][r] = 0.f; }

        #define RUN_PATH(ACC, A_HI_OFF, W_HI_OFF)                              \
        do {                                                                   \
            const uint32_t ah_base = sb + (A_HI_OFF) + aoff;                   \
            const uint32_t al_base = ah_base + 18432;                          \
            _Pragma("unroll")                                                  \
            for (int ks = 0; ks < 4; ks++) {                                   \
                uint32_t ah[4], al[4];                                         \
                ldm_x4(ah, ah_base + ks * 32);                                 \
                ldm_x4(al, al_base + ks * 32);                                 \
                _Pragma("unroll")                                              \
                for (int nt = 0; nt < 8; nt++) {                               \
                    const char* wp = smem + (W_HI_OFF) +                       \
                        (nt * 8 + gid) * WPITCH_B + ks * 32 + 4 * tig;         \
                    const uint32_t wh0 = *(const uint32_t*)(wp);               \
                    const uint32_t wh1 = *(const uint32_t*)(wp + 16);          \
                    const uint32_t wl0 = *(const uint32_t*)(wp + 9216);        \
                    const uint32_t wl1 = *(const uint32_t*)(wp + 9216 + 16);   \
                    mma16816(ACC[nt], ah, wh0, wh1);                           \
                    mma16816(ACC[nt], ah, wl0, wl1);                           \
                    mma16816(ACC[nt], al, wh0, wh1);                           \
                }                                                              \
            }                                                                  \
        } while (0)

        RUN_PATH(accb, OFF_AB_HI, OFF_WB_HI);
        RUN_PATH(accg, OFF_AG_HI, OFF_WG_HI);
        #undef RUN_PATH

        __syncthreads();   // all A reads done; sred may overwrite A region

        // ---- epilogue: bias + gate, stage to sred[m][c] ----
        {
            const int r0 = m0 + gid;
            const int r1 = r0 + 8;
            #pragma unroll
            for (int nt = 0; nt < 8; nt++) {
                const int c0 = nt * 8 + 2 * tig;
                const float bb0 = sbb2[c0], bb1v = sbb2[c0 + 1];
                const float gb0 = sbbg2[c0], gb1 = sbbg2[c0 + 1];
                const float v0 = (accb[nt][0] + bb0)  * fast_sigmoid(accg[nt][0] + gb0);
                const float v1 = (accb[nt][1] + bb1v) * fast_sigmoid(accg[nt][1] + gb1);
                const float v2 = (accb[nt][2] + bb0)  * fast_sigmoid(accg[nt][2] + gb0);
                const float v3 = (accb[nt][3] + bb1v) * fast_sigmoid(accg[nt][3] + gb1);
                *(float2*)(sredf + r0 * SRED_PITCH + c0) = make_float2(v0, v1);
                *(float2*)(sredf + r1 * SRED_PITCH + c0) = make_float2(v2, v3);
            }
        }
        __syncthreads();

        // ---- reduce over i (64 rows) per j, add U, store ----
        if (tid < 128) {
            const int jj = tid >> 6;
            const int c  = tid & 63;
            float s0 = 0.f, s1 = 0.f, s2 = 0.f, s3 = 0.f;
            #pragma unroll
            for (int i4 = 0; i4 < 64; i4 += 4) {
                s0 += sredf[(jj * 64 + i4 + 0) * SRED_PITCH + c];
                s1 += sredf[(jj * 64 + i4 + 1) * SRED_PITCH + c];
                s2 += sredf[(jj * 64 + i4 + 2) * SRED_PITCH + c];
                s3 += sredf[(jj * 64 + i4 + 3) * SRED_PITCH + c];
            }
            const float sum = (s0 + s1) + (s2 + s3);
            const int j = j0 + jj;
            const int o = (n * 64 + j) * 64 + c;
            out[o] = g_U[o] + sum * (1.0f / 63.0f);
        }
        __syncthreads();   // sred (= A region) rebuilt next tile
    }
}

// ---------------------------------------------------------------------------
// launch
// ---------------------------------------------------------------------------
extern "C" void kernel_launch(void* const* d_in, const int* in_sizes, int n_in,
                              void* d_out, int out_size)
{
    const float* x    = (const float*)d_in[0];
    const float* Wlin = (const float*)d_in[1];
    const float* blin = (const float*)d_in[2];
    const float* Wu1  = (const float*)d_in[3];
    const float* bu1  = (const float*)d_in[4];
    const float* Wu2  = (const float*)d_in[5];
    const float* bu2  = (const float*)d_in[6];
    const float* Wug1 = (const float*)d_in[7];
    const float* bug1 = (const float*)d_in[8];
    const float* Wug2 = (const float*)d_in[9];
    const float* bug2 = (const float*)d_in[10];
    const float* Wb1  = (const float*)d_in[11];
    const float* bb1  = (const float*)d_in[12];
    const float* Wb2  = (const float*)d_in[13];
    const float* bb2  = (const float*)d_in[14];
    const float* Wbg1 = (const float*)d_in[15];
    const float* bbg1 = (const float*)d_in[16];
    const float* Wbg2 = (const float*)d_in[17];
    const float* bbg2 = (const float*)d_in[18];

    float* out = (float*)d_out;

    const int prep_smem = PREP_SMEM_FLOATS * (int)sizeof(float);
    cudaFuncSetAttribute(prep_kernel, cudaFuncAttributeMaxDynamicSharedMemorySize, prep_smem);
    cudaFuncSetAttribute(main_kernel, cudaFuncAttributeMaxDynamicSharedMemorySize, MAIN_SMEM_BYTES);

    prep_kernel<<<128, 256, prep_smem>>>(x, Wlin, blin, Wu1, bu1, Wu2, bu2,
                                         Wug1, bug1, Wug2, bug2,
                                         Wb1, bb1, Wbg1, bbg1);
    main_kernel<<<1024, 256, MAIN_SMEM_BYTES>>>(Wb2, bb2, Wbg2, bbg2, out);
}

// round 6
// speedup vs baseline: 1.6604x; 1.1173x over previous
#include <cuda_runtime.h>
#include <cuda_bf16.h>
#include <math.h>
#include <cstdint>

// Problem constants
#define N_ 128
#define K_ 64
#define C_ 64
#define ROWS_ (N_ * K_)   // 8192

// Scratch (device globals: no allocation allowed)
__device__ float g_U [ROWS_ * C_];   // um * ug
__device__ float g_A [ROWS_ * C_];   // h @ Wb1[:C]  + bb1
__device__ float g_B [ROWS_ * C_];   // h @ Wb1[C:]
__device__ float g_Ag[ROWS_ * C_];   // h @ Wbg1[:C] + bbg1
__device__ float g_Bg[ROWS_ * C_];   // h @ Wbg1[C:]

__device__ __forceinline__ float fast_tanh(float x) {
    return 1.0f - __fdividef(2.0f, __expf(2.0f * x) + 1.0f);
}
__device__ __forceinline__ float fast_sigmoid(float x) {
    return __fdividef(1.0f, 1.0f + __expf(-x));
}

// pack two fp32 into bf16x2 (first arg -> low 16 bits)
__device__ __forceinline__ uint32_t pack_bf16x2(float lo, float hi) {
    uint32_t r;
    asm("cvt.rn.bf16x2.f32 %0, %1, %2;" : "=r"(r) : "f"(hi), "f"(lo));
    return r;
}

__device__ __forceinline__ uint32_t smem_to_u32(const void* p) {
    uint32_t a;
    asm("{ .reg .u64 t; cvta.to.shared.u64 t, %1; cvt.u32.u64 %0, t; }"
        : "=r"(a) : "l"(p));
    return a;
}

// warp-level bf16 HMMA, m16n8k16, row.col, f32 accumulate (base-target PTX)
__device__ __forceinline__ void mma16816(float acc[4], const uint32_t a[4],
                                         uint32_t b0, uint32_t b1) {
    asm volatile(
        "mma.sync.aligned.m16n8k16.row.col.f32.bf16.bf16.f32 "
        "{%0,%1,%2,%3}, {%4,%5,%6,%7}, {%8,%9}, {%0,%1,%2,%3};"
        : "+f"(acc[0]), "+f"(acc[1]), "+f"(acc[2]), "+f"(acc[3])
        : "r"(a[0]), "r"(a[1]), "r"(a[2]), "r"(a[3]), "r"(b0), "r"(b1));
}

__device__ __forceinline__ void ldm_x4(uint32_t r[4], uint32_t addr) {
    asm volatile(
        "ldmatrix.sync.aligned.m8n8.x4.shared.b16 {%0,%1,%2,%3}, [%4];"
        : "=r"(r[0]), "=r"(r[1]), "=r"(r[2]), "=r"(r[3]) : "r"(addr));
}

// ---------------------------------------------------------------------------
// Kernel 1: h, unary path U, binary factors A/B/Ag/Bg.
// 512 threads: 8 rows x 64 channels per pass, 8 passes per block.
// ---------------------------------------------------------------------------
#define PREP_SMEM_FLOATS (9 * 4096 + 3 * 512)

__global__ __launch_bounds__(512)
void prep_kernel(const float* __restrict__ x,
                 const float* __restrict__ Wlin, const float* __restrict__ blin,
                 const float* __restrict__ Wu1,  const float* __restrict__ bu1,
                 const float* __restrict__ Wu2,  const float* __restrict__ bu2,
                 const float* __restrict__ Wug1, const float* __restrict__ bug1,
                 const float* __restrict__ Wug2, const float* __restrict__ bug2,
                 const float* __restrict__ Wb1,  const float* __restrict__ bb1,
                 const float* __restrict__ Wbg1, const float* __restrict__ bbg1)
{
    extern __shared__ float sm[];
    float* sWlin  = sm;
    float* sWu1   = sm + 4096;
    float* sWu2   = sm + 2 * 4096;
    float* sWug1  = sm + 3 * 4096;
    float* sWug2  = sm + 4 * 4096;
    float* sWb1a  = sm + 5 * 4096;
    float* sWb1b  = sm + 6 * 4096;
    float* sWbg1a = sm + 7 * 4096;
    float* sWbg1b = sm + 8 * 4096;
    float* sx     = sm + 9 * 4096;   // [8][64]
    float* sh     = sx + 512;        // [8][64]
    float* st     = sh + 512;        // [8][64]

    const int tid = threadIdx.x;
    for (int i = tid; i < 4096; i += 512) {
        sWlin[i]  = Wlin[i];
        sWu1[i]   = Wu1[i];
        sWu2[i]   = Wu2[i];
        sWug1[i]  = Wug1[i];
        sWug2[i]  = Wug2[i];
        sWb1a[i]  = Wb1[i];
        sWb1b[i]  = Wb1[4096 + i];
        sWbg1a[i] = Wbg1[i];
        sWbg1b[i] = Wbg1[4096 + i];
    }
    __syncthreads();

    const int rr = tid >> 6;     // 0..7
    const int c  = tid & 63;
    const int row0 = blockIdx.x * 64;

    for (int g = 0; g < 8; g++) {
        const int row = row0 + g * 8 + rr;
        sx[rr * 64 + c] = x[row * 64 + c];
        __syncthreads();

        float acc = blin[c];
        #pragma unroll 16
        for (int k = 0; k < 64; k++)
            acc = fmaf(sx[rr * 64 + k], sWlin[k * 64 + c], acc);
        sh[rr * 64 + c] = acc;
        __syncthreads();

        acc = bu1[c];
        #pragma unroll 16
        for (int k = 0; k < 64; k++)
            acc = fmaf(sh[rr * 64 + k], sWu1[k * 64 + c], acc);
        st[rr * 64 + c] = fast_tanh(acc);
        __syncthreads();

        float um = bu2[c];
        #pragma unroll 16
        for (int k = 0; k < 64; k++)
            um = fmaf(st[rr * 64 + k], sWu2[k * 64 + c], um);
        __syncthreads();

        acc = bug1[c];
        #pragma unroll 16
        for (int k = 0; k < 64; k++)
            acc = fmaf(sh[rr * 64 + k], sWug1[k * 64 + c], acc);
        st[rr * 64 + c] = fast_tanh(acc);
        __syncthreads();

        float ug = bug2[c];
        #pragma unroll 16
        for (int k = 0; k < 64; k++)
            ug = fmaf(st[rr * 64 + k], sWug2[k * 64 + c], ug);
        ug = fast_sigmoid(ug);

        g_U[row * 64 + c] = um * ug;

        float a  = bb1[c];
        float b  = 0.0f;
        float ag = bbg1[c];
        float bg = 0.0f;
        #pragma unroll 16
        for (int k = 0; k < 64; k++) {
            const float hv = sh[rr * 64 + k];
            a  = fmaf(hv, sWb1a [k * 64 + c], a);
            b  = fmaf(hv, sWb1b [k * 64 + c], b);
            ag = fmaf(hv, sWbg1a[k * 64 + c], ag);
            bg = fmaf(hv, sWbg1b[k * 64 + c], bg);
        }
        g_A [row * 64 + c] = a;
        g_B [row * 64 + c] = b;
        g_Ag[row * 64 + c] = ag;
        g_Bg[row * 64 + c] = bg;
        __syncthreads();
    }
}

// ---------------------------------------------------------------------------
// Kernel 2: one block per (n, 8 j's) = 4 tiles of 2 j's.
// Per tile: A[m][k] = tanh(A_j(m)[k] + B_i(m)[k]), m = jj*64+i (M=128,K=64).
// Warps 0-3: path-b, 32-row m-strips; warps 4-7: path-g, same strips.
// 3-pass bf16 hi/lo split per path. Epilogue: path-b stages acc+bias to smem,
// path-g gates + shfl-reduces over i; 128 threads finalize.
// ---------------------------------------------------------------------------
#define WPITCH_B  144                      // 72 bf16 per row
#define OFF_WB_HI 0
#define OFF_WB_LO 9216
#define OFF_WG_HI 18432
#define OFF_WG_LO 27648
#define OFF_AB_HI 36864
#define OFF_AB_LO 55296
#define OFF_AG_HI 73728
#define OFF_AG_LO 92160
#define OFF_BB2   110592
#define OFF_BBG2  110848
#define MAIN_SMEM_BYTES 111104
#define OFF_SV    36864                    // aliases A-b (dead after MMA)
#define SV_PITCH  72                       // floats; 128*72*4 = 36864 B
#define OFF_PART  73728                    // aliases A-g head (4*64*4 = 1 KB)

__global__ __launch_bounds__(256, 2)
void main_kernel(const float* __restrict__ Wb2,  const float* __restrict__ bb2,
                 const float* __restrict__ Wbg2, const float* __restrict__ bbg2,
                 float* __restrict__ out)
{
    extern __shared__ char smem[];
    const uint32_t sb = smem_to_u32(smem);
    const int tid  = threadIdx.x;
    const int wid  = tid >> 5;
    const int lane = tid & 31;
    const int gid  = lane >> 2;
    const int tig  = lane & 3;
    const int n    = blockIdx.x >> 3;
    const int jg   = blockIdx.x & 7;

    // --- one-time: W^T bf16 hi/lo for both paths; biases ---
    for (int idx = tid; idx < 4096; idx += 256) {
        const int k = idx >> 6, c = idx & 63;
        const int off = c * WPITCH_B + k * 2;
        {
            const float w = Wb2[idx];
            const __nv_bfloat16 h = __float2bfloat16(w);
            const __nv_bfloat16 l = __float2bfloat16(w - __bfloat162float(h));
            *(__nv_bfloat16*)(smem + OFF_WB_HI + off) = h;
            *(__nv_bfloat16*)(smem + OFF_WB_LO + off) = l;
        }
        {
            const float w = Wbg2[idx];
            const __nv_bfloat16 h = __float2bfloat16(w);
            const __nv_bfloat16 l = __float2bfloat16(w - __bfloat162float(h));
            *(__nv_bfloat16*)(smem + OFF_WG_HI + off) = h;
            *(__nv_bfloat16*)(smem + OFF_WG_LO + off) = l;
        }
    }
    float* sbb2  = (float*)(smem + OFF_BB2);
    float* sbbg2 = (float*)(smem + OFF_BBG2);
    if (tid < 64) { sbb2[tid] = bb2[tid]; sbbg2[tid] = bbg2[tid]; }
    __syncthreads();

    // phase-1 mapping: (row, part); coalesced 32B-per-row loads
    const int row1  = tid >> 1;              // 0..127
    const int part1 = tid & 1;
    const int jj1   = row1 >> 6;
    const int i1    = row1 & 63;
    const int swz1  = ((row1 >> 3) & 1) * 4; // chunk xor

    // MMA mapping: warps specialize by path, 32-row strips
    const bool pathg = (wid >= 4);
    const int  m0    = 32 * (wid & 3);
    const uint32_t Wbase = sb + (pathg ? OFF_WG_HI : OFF_WB_HI);
    const uint32_t Ahib  = sb + (pathg ? OFF_AG_HI : OFF_AB_HI);
    const int  arow0 = m0 + (lane & 15);
    const int  lsw   = ((lane >> 3) & 1) * 4;
    const int  lch   = lane >> 4;

    float* sV    = (float*)(smem + OFF_SV);
    float* partS = (float*)(smem + OFF_PART);

    for (int t = 0; t < 4; t++) {
        const int j0 = jg * 8 + 2 * t;

        // ---- phase 1: build bf16 hi/lo A tiles (both paths) ----
        #pragma unroll
        for (int p = 0; p < 2; p++) {
            const float* Bbase = (p ? g_Bg : g_B) + (n * 64 + i1) * 64;
            const float* Abase = (p ? g_Ag : g_A) + (n * 64 + j0 + jj1) * 64;
            char* hiB = smem + (p ? OFF_AG_HI : OFF_AB_HI) + row1 * WPITCH_B;
            char* loB = hiB + 18432;
            #pragma unroll
            for (int q = 0; q < 8; q++) {
                const int k0 = q * 8 + part1 * 4;
                const float4 b = *(const float4*)(Bbase + k0);
                const float4 a = *(const float4*)(Abase + k0);
                const float t0 = fast_tanh(a.x + b.x);
                const float t1 = fast_tanh(a.y + b.y);
                const float t2 = fast_tanh(a.z + b.z);
                const float t3 = fast_tanh(a.w + b.w);
                const uint32_t h0 = pack_bf16x2(t0, t1);
                const uint32_t h1 = pack_bf16x2(t2, t3);
                const float hf0 = __uint_as_float(h0 << 16);
                const float hf1 = __uint_as_float(h0 & 0xFFFF0000u);
                const float hf2 = __uint_as_float(h1 << 16);
                const float hf3 = __uint_as_float(h1 & 0xFFFF0000u);
                const uint32_t l0 = pack_bf16x2(t0 - hf0, t1 - hf1);
                const uint32_t l1 = pack_bf16x2(t2 - hf2, t3 - hf3);
                const int boff = ((q ^ swz1) * 16) + part1 * 8;
                *(uint2*)(hiB + boff) = make_uint2(h0, h1);
                *(uint2*)(loB + boff) = make_uint2(l0, l1);
            }
        }
        __syncthreads();

        // ---- MMA: one path, 32-row strip, full N=64, 3-pass bf16 split ----
        float acc[2][8][4];
        #pragma unroll
        for (int s = 0; s < 2; s++)
            #pragma unroll
            for (int nt = 0; nt < 8; nt++)
                #pragma unroll
                for (int r = 0; r < 4; r++) acc[s][nt][r] = 0.f;

        #pragma unroll
        for (int ks = 0; ks < 4; ks++) {
            uint32_t ah0[4], al0[4], ah1[4], al1[4];
            const uint32_t chunk = (uint32_t)((((ks * 2 + lch) ^ lsw)) * 16);
            const uint32_t ad0 = Ahib + (uint32_t)(arow0 * WPITCH_B) + chunk;
            const uint32_t ad1 = ad0 + 16 * WPITCH_B;
            ldm_x4(ah0, ad0);
            ldm_x4(al0, ad0 + 18432);
            ldm_x4(ah1, ad1);
            ldm_x4(al1, ad1 + 18432);
            #pragma unroll
            for (int nt = 0; nt < 8; nt++) {
                const char* wp = (const char*)smem +
                    (Wbase - sb) + (nt * 8 + gid) * WPITCH_B + ks * 32 + 4 * tig;
                const uint32_t wh0 = *(const uint32_t*)(wp);
                const uint32_t wh1 = *(const uint32_t*)(wp + 16);
                const uint32_t wl0 = *(const uint32_t*)(wp + 9216);
                const uint32_t wl1 = *(const uint32_t*)(wp + 9216 + 16);
                mma16816(acc[0][nt], ah0, wh0, wh1);
                mma16816(acc[0][nt], ah0, wl0, wl1);
                mma16816(acc[0][nt], al0, wh0, wh1);
                mma16816(acc[1][nt], ah1, wh0, wh1);
                mma16816(acc[1][nt], ah1, wl0, wl1);
                mma16816(acc[1][nt], al1, wh0, wh1);
            }
        }
        __syncthreads();   // all ldmatrix reads done; A regions reusable

        // ---- path-b: stage acc+bias to sV[m][c] ----
        if (!pathg) {
            #pragma unroll
            for (int nt = 0; nt < 8; nt++) {
                const int c0 = nt * 8 + 2 * tig;
                const float2 bb = *(const float2*)(sbb2 + c0);
                #pragma unroll
                for (int s = 0; s < 2; s++) {
                    const int ra = m0 + 16 * s + gid;
                    *(float2*)(sV + ra * SV_PITCH + c0) =
                        make_float2(acc[s][nt][0] + bb.x, acc[s][nt][1] + bb.y);
                    *(float2*)(sV + (ra + 8) * SV_PITCH + c0) =
                        make_float2(acc[s][nt][2] + bb.x, acc[s][nt][3] + bb.y);
                }
            }
        }
        __syncthreads();

        // ---- path-g: gate, multiply, shfl-reduce over 32 i-rows ----
        if (pathg) {
            const int wg = wid - 4;
            #pragma unroll
            for (int nt = 0; nt < 8; nt++) {
                const int c0 = nt * 8 + 2 * tig;
                const float2 gb = *(const float2*)(sbbg2 + c0);
                float p0 = 0.f, p1 = 0.f;
                #pragma unroll
                for (int s = 0; s < 2; s++) {
                    const int ra = m0 + 16 * s + gid;
                    const float2 va = *(const float2*)(sV + ra * SV_PITCH + c0);
                    const float2 vb = *(const float2*)(sV + (ra + 8) * SV_PITCH + c0);
                    p0 += fast_sigmoid(acc[s][nt][0] + gb.x) * va.x;
                    p1 += fast_sigmoid(acc[s][nt][1] + gb.y) * va.y;
                    p0 += fast_sigmoid(acc[s][nt][2] + gb.x) * vb.x;
                    p1 += fast_sigmoid(acc[s][nt][3] + gb.y) * vb.y;
                }
                p0 += __shfl_xor_sync(0xFFFFFFFFu, p0, 4);
                p1 += __shfl_xor_sync(0xFFFFFFFFu, p1, 4);
                p0 += __shfl_xor_sync(0xFFFFFFFFu, p0, 8);
                p1 += __shfl_xor_sync(0xFFFFFFFFu, p1, 8);
                p0 += __shfl_xor_sync(0xFFFFFFFFu, p0, 16);
                p1 += __shfl_xor_sync(0xFFFFFFFFu, p1, 16);
                if (lane < 4) {
                    partS[wg * 64 + c0]     = p0;
                    partS[wg * 64 + c0 + 1] = p1;
                }
            }
        }
        __syncthreads();

        // ---- finalize: sum i-halves, add U, store ----
        if (tid < 128) {
            const int jj = tid >> 6;
            const int c  = tid & 63;
            const float sum = partS[(2 * jj) * 64 + c] + partS[(2 * jj + 1) * 64 + c];
            const int o = (n * 64 + j0 + jj) * 64 + c;
            out[o] = g_U[o] + sum * (1.0f / 63.0f);
        }
        __syncthreads();   // A / sV / part regions rebuilt next tile
    }
}

// ---------------------------------------------------------------------------
// launch
// ---------------------------------------------------------------------------
extern "C" void kernel_launch(void* const* d_in, const int* in_sizes, int n_in,
                              void* d_out, int out_size)
{
    const float* x    = (const float*)d_in[0];
    const float* Wlin = (const float*)d_in[1];
    const float* blin = (const float*)d_in[2];
    const float* Wu1  = (const float*)d_in[3];
    const float* bu1  = (const float*)d_in[4];
    const float* Wu2  = (const float*)d_in[5];
    const float* bu2  = (const float*)d_in[6];
    const float* Wug1 = (const float*)d_in[7];
    const float* bug1 = (const float*)d_in[8];
    const float* Wug2 = (const float*)d_in[9];
    const float* bug2 = (const float*)d_in[10];
    const float* Wb1  = (const float*)d_in[11];
    const float* bb1  = (const float*)d_in[12];
    const float* Wb2  = (const float*)d_in[13];
    const float* bb2  = (const float*)d_in[14];
    const float* Wbg1 = (const float*)d_in[15];
    const float* bbg1 = (const float*)d_in[16];
    const float* Wbg2 = (const float*)d_in[17];
    const float* bbg2 = (const float*)d_in[18];

    float* out = (float*)d_out;

    const int prep_smem = PREP_SMEM_FLOATS * (int)sizeof(float);
    cudaFuncSetAttribute(prep_kernel, cudaFuncAttributeMaxDynamicSharedMemorySize, prep_smem);
    cudaFuncSetAttribute(main_kernel, cudaFuncAttributeMaxDynamicSharedMemorySize, MAIN_SMEM_BYTES);

    prep_kernel<<<128, 512, prep_smem>>>(x, Wlin, blin, Wu1, bu1, Wu2, bu2,
                                         Wug1, bug1, Wug2, bug2,
                                         Wb1, bb1, Wbg1, bbg1);
    main_kernel<<<1024, 256, MAIN_SMEM_BYTES>>>(Wb2, bb2, Wbg2, bbg2, out);
}

// round 7
// speedup vs baseline: 2.0432x; 1.2305x over previous
#include <cuda_runtime.h>
#include <cuda_bf16.h>
#include <math.h>
#include <cstdint>

// Problem constants
#define N_ 128
#define K_ 64
#define C_ 64
#define ROWS_ (N_ * K_)   // 8192

// Scratch (device globals: no allocation allowed)
__device__ float g_U [ROWS_ * C_];   // um * ug
__device__ float g_A [ROWS_ * C_];   // h @ Wb1[:C]  + bb1
__device__ float g_B [ROWS_ * C_];   // h @ Wb1[C:]
__device__ float g_Ag[ROWS_ * C_];   // h @ Wbg1[:C] + bbg1
__device__ float g_Bg[ROWS_ * C_];   // h @ Wbg1[C:]
// Precomputed bf16 hi/lo W image in exact main-kernel smem layout:
// [0,9216) Wb hi | [9216,18432) Wb lo | [18432,27648) Wg hi | [27648,36864) Wg lo
__device__ unsigned char g_Wimg[36864];

__device__ __forceinline__ float fast_tanh(float x) {
    return 1.0f - __fdividef(2.0f, __expf(2.0f * x) + 1.0f);
}
__device__ __forceinline__ float fast_sigmoid(float x) {
    return __fdividef(1.0f, 1.0f + __expf(-x));
}

// pack two fp32 into bf16x2 (first arg -> low 16 bits)
__device__ __forceinline__ uint32_t pack_bf16x2(float lo, float hi) {
    uint32_t r;
    asm("cvt.rn.bf16x2.f32 %0, %1, %2;" : "=r"(r) : "f"(hi), "f"(lo));
    return r;
}

__device__ __forceinline__ uint32_t smem_to_u32(const void* p) {
    uint32_t a;
    asm("{ .reg .u64 t; cvta.to.shared.u64 t, %1; cvt.u32.u64 %0, t; }"
        : "=r"(a) : "l"(p));
    return a;
}

// warp-level bf16 HMMA, m16n8k16, row.col, f32 accumulate (base-target PTX)
__device__ __forceinline__ void mma16816(float acc[4], const uint32_t a[4],
                                         uint32_t b0, uint32_t b1) {
    asm volatile(
        "mma.sync.aligned.m16n8k16.row.col.f32.bf16.bf16.f32 "
        "{%0,%1,%2,%3}, {%4,%5,%6,%7}, {%8,%9}, {%0,%1,%2,%3};"
        : "+f"(acc[0]), "+f"(acc[1]), "+f"(acc[2]), "+f"(acc[3])
        : "r"(a[0]), "r"(a[1]), "r"(a[2]), "r"(a[3]), "r"(b0), "r"(b1));
}

__device__ __forceinline__ void ldm_x4(uint32_t r[4], uint32_t addr) {
    asm volatile(
        "ldmatrix.sync.aligned.m8n8.x4.shared.b16 {%0,%1,%2,%3}, [%4];"
        : "=r"(r[0]), "=r"(r[1]), "=r"(r[2]), "=r"(r[3]) : "r"(addr));
}

// ---------------------------------------------------------------------------
// Kernel 1 (warp-autonomous): blocks 0..127 compute h, unary U, binary
// factors A/B/Ag/Bg with ZERO block barriers in the row loop (per-warp smem
// ping-pong buffers + __syncwarp). Block 128 builds the bf16 W image.
// ---------------------------------------------------------------------------
#define PREP_SMEM_FLOATS (9 * 4096 + 16 * 128)

#define GEMV2(dst, buf, W, bias)                                         \
    {                                                                    \
        dst = bias;                                                      \
        _Pragma("unroll 8")                                              \
        for (int k2 = 0; k2 < 32; k2++) {                                \
            const float2 v  = *(const float2*)((buf) + 2 * k2);          \
            const float2 w0 = *(const float2*)((W) + (2*k2)   * 64 + c0);\
            const float2 w1 = *(const float2*)((W) + (2*k2+1) * 64 + c0);\
            dst.x = fmaf(v.x, w0.x, fmaf(v.y, w1.x, dst.x));             \
            dst.y = fmaf(v.x, w0.y, fmaf(v.y, w1.y, dst.y));             \
        }                                                                \
    }

__global__ __launch_bounds__(512)
void prep_kernel(const float* __restrict__ x,
                 const float* __restrict__ Wlin, const float* __restrict__ blin,
                 const float* __restrict__ Wu1,  const float* __restrict__ bu1,
                 const float* __restrict__ Wu2,  const float* __restrict__ bu2,
                 const float* __restrict__ Wug1, const float* __restrict__ bug1,
                 const float* __restrict__ Wug2, const float* __restrict__ bug2,
                 const float* __restrict__ Wb1,  const float* __restrict__ bb1,
                 const float* __restrict__ Wbg1, const float* __restrict__ bbg1,
                 const float* __restrict__ Wb2,  const float* __restrict__ Wbg2)
{
    const int tid = threadIdx.x;

    // --- block 128: build bf16 hi/lo W image for main kernel ---
    if (blockIdx.x == 128) {
        for (int idx = tid; idx < 4096; idx += 512) {
            const int k = idx >> 6, c = idx & 63;
            const int off = c * 144 + k * 2;
            {
                const float w = Wb2[idx];
                const __nv_bfloat16 h = __float2bfloat16(w);
                const __nv_bfloat16 l = __float2bfloat16(w - __bfloat162float(h));
                *(__nv_bfloat16*)(g_Wimg + off)        = h;
                *(__nv_bfloat16*)(g_Wimg + 9216 + off) = l;
            }
            {
                const float w = Wbg2[idx];
                const __nv_bfloat16 h = __float2bfloat16(w);
                const __nv_bfloat16 l = __float2bfloat16(w - __bfloat162float(h));
                *(__nv_bfloat16*)(g_Wimg + 18432 + off) = h;
                *(__nv_bfloat16*)(g_Wimg + 27648 + off) = l;
            }
        }
        return;
    }

    extern __shared__ float sm[];
    float* sWlin  = sm;
    float* sWu1   = sm + 4096;
    float* sWu2   = sm + 2 * 4096;
    float* sWug1  = sm + 3 * 4096;
    float* sWug2  = sm + 4 * 4096;
    float* sWb1a  = sm + 5 * 4096;
    float* sWb1b  = sm + 6 * 4096;
    float* sWbg1a = sm + 7 * 4096;
    float* sWbg1b = sm + 8 * 4096;
    float* bufs   = sm + 9 * 4096;   // [16 warps][2][64]

    for (int i = tid; i < 4096; i += 512) {
        sWlin[i]  = Wlin[i];
        sWu1[i]   = Wu1[i];
        sWu2[i]   = Wu2[i];
        sWug1[i]  = Wug1[i];
        sWug2[i]  = Wug2[i];
        sWb1a[i]  = Wb1[i];
        sWb1b[i]  = Wb1[4096 + i];
        sWbg1a[i] = Wbg1[i];
        sWbg1b[i] = Wbg1[4096 + i];
    }
    __syncthreads();   // the only block barrier

    const int w    = tid >> 5;
    const int lane = tid & 31;
    const int c0   = 2 * lane;
    float* buf0 = bufs + w * 128;
    float* buf1 = buf0 + 64;

    const float2 blin2 = *(const float2*)(blin + c0);
    const float2 bu12  = *(const float2*)(bu1  + c0);
    const float2 bu22  = *(const float2*)(bu2  + c0);
    const float2 bug12 = *(const float2*)(bug1 + c0);
    const float2 bug22 = *(const float2*)(bug2 + c0);
    const float2 bb12  = *(const float2*)(bb1  + c0);
    const float2 bbg12 = *(const float2*)(bbg1 + c0);

    for (int r = 0; r < 4; r++) {
        const int row = blockIdx.x * 64 + w * 4 + r;

        // x row -> buf0
        *(float2*)(buf0 + c0) = *(const float2*)(x + row * 64 + c0);
        __syncwarp();

        // h = x @ Wlin + blin  -> buf1
        float2 h;  GEMV2(h, buf0, sWlin, blin2);
        __syncwarp();
        *(float2*)(buf1 + c0) = h;
        __syncwarp();

        // t1 = tanh(h @ Wu1 + bu1) -> buf0
        float2 a1; GEMV2(a1, buf1, sWu1, bu12);
        a1.x = fast_tanh(a1.x); a1.y = fast_tanh(a1.y);
        __syncwarp();
        *(float2*)(buf0 + c0) = a1;
        __syncwarp();

        // um = t1 @ Wu2 + bu2
        float2 um; GEMV2(um, buf0, sWu2, bu22);

        // t2 = tanh(h @ Wug1 + bug1) -> buf0
        float2 a2; GEMV2(a2, buf1, sWug1, bug12);
        a2.x = fast_tanh(a2.x); a2.y = fast_tanh(a2.y);
        __syncwarp();
        *(float2*)(buf0 + c0) = a2;
        __syncwarp();

        // ug = sigmoid(t2 @ Wug2 + bug2); U = um * ug
        float2 ug; GEMV2(ug, buf0, sWug2, bug22);
        float2 U;
        U.x = um.x * fast_sigmoid(ug.x);
        U.y = um.y * fast_sigmoid(ug.y);
        *(float2*)(g_U + row * 64 + c0) = U;

        // binary first-layer factors (4 GEMVs over buf1)
        float2 fa = bb12, fb = make_float2(0.f, 0.f);
        float2 fag = bbg12, fbg = make_float2(0.f, 0.f);
        #pragma unroll 8
        for (int k2 = 0; k2 < 32; k2++) {
            const float2 v = *(const float2*)(buf1 + 2 * k2);
            const int r0 = (2 * k2) * 64 + c0, r1 = (2 * k2 + 1) * 64 + c0;
            const float2 wa0 = *(const float2*)(sWb1a  + r0);
            const float2 wa1 = *(const float2*)(sWb1a  + r1);
            const float2 wb0 = *(const float2*)(sWb1b  + r0);
            const float2 wb1 = *(const float2*)(sWb1b  + r1);
            const float2 wc0 = *(const float2*)(sWbg1a + r0);
            const float2 wc1 = *(const float2*)(sWbg1a + r1);
            const float2 wd0 = *(const float2*)(sWbg1b + r0);
            const float2 wd1 = *(const float2*)(sWbg1b + r1);
            fa.x  = fmaf(v.x, wa0.x, fmaf(v.y, wa1.x, fa.x));
            fa.y  = fmaf(v.x, wa0.y, fmaf(v.y, wa1.y, fa.y));
            fb.x  = fmaf(v.x, wb0.x, fmaf(v.y, wb1.x, fb.x));
            fb.y  = fmaf(v.x, wb0.y, fmaf(v.y, wb1.y, fb.y));
            fag.x = fmaf(v.x, wc0.x, fmaf(v.y, wc1.x, fag.x));
            fag.y = fmaf(v.x, wc0.y, fmaf(v.y, wc1.y, fag.y));
            fbg.x = fmaf(v.x, wd0.x, fmaf(v.y, wd1.x, fbg.x));
            fbg.y = fmaf(v.x, wd0.y, fmaf(v.y, wd1.y, fbg.y));
        }
        *(float2*)(g_A  + row * 64 + c0) = fa;
        *(float2*)(g_B  + row * 64 + c0) = fb;
        *(float2*)(g_Ag + row * 64 + c0) = fag;
        *(float2*)(g_Bg + row * 64 + c0) = fbg;
        __syncwarp();   // before next row overwrites buffers
    }
}

// ---------------------------------------------------------------------------
// Kernel 2: one block per (n, 4 j's) = 2 tiles of 2 j's. 2048 blocks.
// Per tile: A[m][k] = tanh(A_j(m)[k] + B_i(m)[k]), m = jj*64+i (M=128,K=64).
// Each warp: 16-row strip, BOTH paths, 3-pass bf16 hi/lo split, gate fully in
// registers, shfl reduce over its 16 i-rows -> 2 syncs per tile.
// ---------------------------------------------------------------------------
#define WPITCH_B  144
#define OFF_WB_HI 0
#define OFF_WB_LO 9216
#define OFF_WG_HI 18432
#define OFF_WG_LO 27648
#define OFF_AB_HI 36864
#define OFF_AB_LO 55296
#define OFF_AG_HI 73728
#define OFF_AG_LO 92160
#define OFF_BB2   110592
#define OFF_BBG2  110848
#define OFF_PART  111104                   // [8][64] floats = 2048 B
#define MAIN_SMEM_BYTES 113152

__global__ __launch_bounds__(256, 2)
void main_kernel(const float* __restrict__ bb2, const float* __restrict__ bbg2,
                 float* __restrict__ out)
{
    extern __shared__ char smem[];
    const uint32_t sb = smem_to_u32(smem);
    const int tid  = threadIdx.x;
    const int wid  = tid >> 5;
    const int lane = tid & 31;
    const int gid  = lane >> 2;
    const int tig  = lane & 3;
    const int n    = blockIdx.x >> 4;
    const int jg   = blockIdx.x & 15;

    // --- one-time: copy precomputed W image (both paths, hi+lo) ---
    {
        const uint4* wsrc = (const uint4*)g_Wimg;
        uint4* wdst = (uint4*)smem;
        #pragma unroll
        for (int i = 0; i < 9; i++)
            wdst[tid + 256 * i] = wsrc[tid + 256 * i];
    }
    float* sbb2  = (float*)(smem + OFF_BB2);
    float* sbbg2 = (float*)(smem + OFF_BBG2);
    if (tid < 64) { sbb2[tid] = bb2[tid]; sbbg2[tid] = bbg2[tid]; }
    __syncthreads();

    // phase-1 mapping: (row, part); coalesced 16B-per-thread loads
    const int row1  = tid >> 1;              // 0..127
    const int part1 = tid & 1;
    const int jj1   = row1 >> 6;
    const int i1    = row1 & 63;
    const int swz1  = ((row1 >> 3) & 1) * 4; // chunk xor

    // MMA mapping: 16-row strips, both paths per warp
    const int m0    = 16 * wid;
    const int arow0 = m0 + (lane & 15);
    const int lsw   = ((lane >> 3) & 1) * 4;
    const int lch   = lane >> 4;

    float* partS = (float*)(smem + OFF_PART);

    for (int t = 0; t < 2; t++) {
        const int j0 = jg * 4 + 2 * t;

        // ---- phase 1: build bf16 hi/lo A tiles (both paths) ----
        #pragma unroll
        for (int p = 0; p < 2; p++) {
            const float* Bbase = (p ? g_Bg : g_B) + (n * 64 + i1) * 64;
            const float* Abase = (p ? g_Ag : g_A) + (n * 64 + j0 + jj1) * 64;
            char* hiB = smem + (p ? OFF_AG_HI : OFF_AB_HI) + row1 * WPITCH_B;
            char* loB = hiB + 18432;
            #pragma unroll
            for (int q = 0; q < 8; q++) {
                const int k0 = q * 8 + part1 * 4;
                const float4 b = *(const float4*)(Bbase + k0);
                const float4 a = *(const float4*)(Abase + k0);
                const float t0 = fast_tanh(a.x + b.x);
                const float t1 = fast_tanh(a.y + b.y);
                const float t2 = fast_tanh(a.z + b.z);
                const float t3 = fast_tanh(a.w + b.w);
                const uint32_t h0 = pack_bf16x2(t0, t1);
                const uint32_t h1 = pack_bf16x2(t2, t3);
                const float hf0 = __uint_as_float(h0 << 16);
                const float hf1 = __uint_as_float(h0 & 0xFFFF0000u);
                const float hf2 = __uint_as_float(h1 << 16);
                const float hf3 = __uint_as_float(h1 & 0xFFFF0000u);
                const uint32_t l0 = pack_bf16x2(t0 - hf0, t1 - hf1);
                const uint32_t l1 = pack_bf16x2(t2 - hf2, t3 - hf3);
                const int boff = ((q ^ swz1) * 16) + part1 * 8;
                *(uint2*)(hiB + boff) = make_uint2(h0, h1);
                *(uint2*)(loB + boff) = make_uint2(l0, l1);
            }
        }
        __syncthreads();   // sync #1

        // ---- MMA: both paths, 16-row strip, full N=64, 3-pass split ----
        float accb[8][4], accg[8][4];
        #pragma unroll
        for (int nt = 0; nt < 8; nt++)
            #pragma unroll
            for (int r = 0; r < 4; r++) { accb[nt][r] = 0.f; accg[nt][r] = 0.f; }

        #pragma unroll
        for (int ks = 0; ks < 4; ks++) {
            const uint32_t chunk = (uint32_t)(((ks * 2 + lch) ^ lsw) * 16);
            const uint32_t adb = sb + OFF_AB_HI + (uint32_t)(arow0 * WPITCH_B) + chunk;
            const uint32_t adg = adb + (OFF_AG_HI - OFF_AB_HI);
            uint32_t ahb[4], alb[4], ahg[4], alg[4];
            ldm_x4(ahb, adb);
            ldm_x4(alb, adb + 18432);
            ldm_x4(ahg, adg);
            ldm_x4(alg, adg + 18432);
            #pragma unroll
            for (int nt = 0; nt < 8; nt++) {
                const char* wpB = (const char*)smem + OFF_WB_HI +
                    (nt * 8 + gid) * WPITCH_B + ks * 32 + 4 * tig;
                const char* wpG = wpB + 18432;
                const uint32_t bh0 = *(const uint32_t*)(wpB);
                const uint32_t bh1 = *(const uint32_t*)(wpB + 16);
                const uint32_t bl0 = *(const uint32_t*)(wpB + 9216);
                const uint32_t bl1 = *(const uint32_t*)(wpB + 9216 + 16);
                const uint32_t gh0 = *(const uint32_t*)(wpG);
                const uint32_t gh1 = *(const uint32_t*)(wpG + 16);
                const uint32_t gl0 = *(const uint32_t*)(wpG + 9216);
                const uint32_t gl1 = *(const uint32_t*)(wpG + 9216 + 16);
                mma16816(accb[nt], ahb, bh0, bh1);
                mma16816(accb[nt], ahb, bl0, bl1);
                mma16816(accb[nt], alb, bh0, bh1);
                mma16816(accg[nt], ahg, gh0, gh1);
                mma16816(accg[nt], ahg, gl0, gl1);
                mma16816(accg[nt], alg, gh0, gh1);
            }
        }

        // ---- epilogue in registers: bias + gate + 16-row reduce ----
        #pragma unroll
        for (int nt = 0; nt < 8; nt++) {
            const int c0 = nt * 8 + 2 * tig;
            const float2 bb = *(const float2*)(sbb2 + c0);
            const float2 gb = *(const float2*)(sbbg2 + c0);
            float p0 = (accb[nt][0] + bb.x) * fast_sigmoid(accg[nt][0] + gb.x)
                     + (accb[nt][2] + bb.x) * fast_sigmoid(accg[nt][2] + gb.x);
            float p1 = (accb[nt][1] + bb.y) * fast_sigmoid(accg[nt][1] + gb.y)
                     + (accb[nt][3] + bb.y) * fast_sigmoid(accg[nt][3] + gb.y);
            p0 += __shfl_xor_sync(0xFFFFFFFFu, p0, 4);
            p1 += __shfl_xor_sync(0xFFFFFFFFu, p1, 4);
            p0 += __shfl_xor_sync(0xFFFFFFFFu, p0, 8);
            p1 += __shfl_xor_sync(0xFFFFFFFFu, p1, 8);
            p0 += __shfl_xor_sync(0xFFFFFFFFu, p0, 16);
            p1 += __shfl_xor_sync(0xFFFFFFFFu, p1, 16);
            if (lane < 4)   // lanes 0..3: gid=0, tig=lane
                *(float2*)(partS + wid * 64 + nt * 8 + 2 * lane) = make_float2(p0, p1);
        }
        __syncthreads();   // sync #2

        // ---- finalize: sum 4 warp-partials per j, add U, store ----
        if (tid < 128) {
            const int jj = tid >> 6;
            const int c  = tid & 63;
            const float sum = partS[(4 * jj + 0) * 64 + c]
                            + partS[(4 * jj + 1) * 64 + c]
                            + partS[(4 * jj + 2) * 64 + c]
                            + partS[(4 * jj + 3) * 64 + c];
            const int o = (n * 64 + j0 + jj) * 64 + c;
            out[o] = g_U[o] + sum * (1.0f / 63.0f);
        }
        // no extra sync: partS(t+1) writes occur only after sync #1 of t+1,
        // which all finalize threads must reach first.
    }
}

// ---------------------------------------------------------------------------
// launch
// ---------------------------------------------------------------------------
extern "C" void kernel_launch(void* const* d_in, const int* in_sizes, int n_in,
                              void* d_out, int out_size)
{
    const float* x    = (const float*)d_in[0];
    const float* Wlin = (const float*)d_in[1];
    const float* blin = (const float*)d_in[2];
    const float* Wu1  = (const float*)d_in[3];
    const float* bu1  = (const float*)d_in[4];
    const float* Wu2  = (const float*)d_in[5];
    const float* bu2  = (const float*)d_in[6];
    const float* Wug1 = (const float*)d_in[7];
    const float* bug1 = (const float*)d_in[8];
    const float* Wug2 = (const float*)d_in[9];
    const float* bug2 = (const float*)d_in[10];
    const float* Wb1  = (const float*)d_in[11];
    const float* bb1  = (const float*)d_in[12];
    const float* Wb2  = (const float*)d_in[13];
    const float* bb2  = (const float*)d_in[14];
    const float* Wbg1 = (const float*)d_in[15];
    const float* bbg1 = (const float*)d_in[16];
    const float* Wbg2 = (const float*)d_in[17];
    const float* bbg2 = (const float*)d_in[18];

    float* out = (float*)d_out;

    const int prep_smem = PREP_SMEM_FLOATS * (int)sizeof(float);   // 155648 B
    cudaFuncSetAttribute(prep_kernel, cudaFuncAttributeMaxDynamicSharedMemorySize, prep_smem);
    cudaFuncSetAttribute(main_kernel, cudaFuncAttributeMaxDynamicSharedMemorySize, MAIN_SMEM_BYTES);

    prep_kernel<<<129, 512, prep_smem>>>(x, Wlin, blin, Wu1, bu1, Wu2, bu2,
                                         Wug1, bug1, Wug2, bug2,
                                         Wb1, bb1, Wbg1, bbg1, Wb2, Wbg2);
    main_kernel<<<2048, 256, MAIN_SMEM_BYTES>>>(bb2, bbg2, out);
}

// round 8
// speedup vs baseline: 2.0642x; 1.0103x over previous
#include <cuda_runtime.h>
#include <cuda_bf16.h>
#include <math.h>
#include <cstdint>

// Problem constants
#define N_ 128
#define K_ 64
#define C_ 64
#define ROWS_ (N_ * K_)   // 8192

// Scratch (device globals: no allocation allowed)
__device__ float g_U [ROWS_ * C_];   // um * ug
__device__ float g_A [ROWS_ * C_];   // h @ Wb1[:C]  + bb1
__device__ float g_B [ROWS_ * C_];   // h @ Wb1[C:]
__device__ float g_Ag[ROWS_ * C_];   // h @ Wbg1[:C] + bbg1
__device__ float g_Bg[ROWS_ * C_];   // h @ Wbg1[C:]
// Precomputed bf16 hi/lo W image in exact main-kernel smem layout:
// [0,9216) Wb hi | [9216,18432) Wb lo | [18432,27648) Wg hi | [27648,36864) Wg lo
__device__ unsigned char g_Wimg[36864];

__device__ __forceinline__ float fast_tanh(float x) {
    return 1.0f - __fdividef(2.0f, __expf(2.0f * x) + 1.0f);
}
__device__ __forceinline__ float fast_sigmoid(float x) {
    return __fdividef(1.0f, 1.0f + __expf(-x));
}

// pack two fp32 into bf16x2 (first arg -> low 16 bits)
__device__ __forceinline__ uint32_t pack_bf16x2(float lo, float hi) {
    uint32_t r;
    asm("cvt.rn.bf16x2.f32 %0, %1, %2;" : "=r"(r) : "f"(hi), "f"(lo));
    return r;
}

__device__ __forceinline__ uint32_t smem_to_u32(const void* p) {
    uint32_t a;
    asm("{ .reg .u64 t; cvta.to.shared.u64 t, %1; cvt.u32.u64 %0, t; }"
        : "=r"(a) : "l"(p));
    return a;
}

// warp-level bf16 HMMA, m16n8k16, row.col, f32 accumulate (base-target PTX)
__device__ __forceinline__ void mma16816(float acc[4], const uint32_t a[4],
                                         uint32_t b0, uint32_t b1) {
    asm volatile(
        "mma.sync.aligned.m16n8k16.row.col.f32.bf16.bf16.f32 "
        "{%0,%1,%2,%3}, {%4,%5,%6,%7}, {%8,%9}, {%0,%1,%2,%3};"
        : "+f"(acc[0]), "+f"(acc[1]), "+f"(acc[2]), "+f"(acc[3])
        : "r"(a[0]), "r"(a[1]), "r"(a[2]), "r"(a[3]), "r"(b0), "r"(b1));
}

__device__ __forceinline__ void ldm_x4(uint32_t r[4], uint32_t addr) {
    asm volatile(
        "ldmatrix.sync.aligned.m8n8.x4.shared.b16 {%0,%1,%2,%3}, [%4];"
        : "=r"(r[0]), "=r"(r[1]), "=r"(r[2]), "=r"(r[3]) : "r"(addr));
}

// ---------------------------------------------------------------------------
// Kernel 1 (warp-autonomous): blocks 0..127 compute h, unary U, binary
// factors A/B/Ag/Bg with ZERO block barriers in the row loop (per-warp smem
// ping-pong buffers + __syncwarp). Block 128 builds the bf16 W image.
// ---------------------------------------------------------------------------
#define PREP_SMEM_FLOATS (9 * 4096 + 16 * 128)

// dual-accumulator GEMV: two independent k-half chains
#define GEMV2(dst, buf, W, bias)                                          \
    {                                                                     \
        float2 aA = bias;                                                 \
        float2 aB = make_float2(0.f, 0.f);                                \
        _Pragma("unroll 8")                                               \
        for (int k2 = 0; k2 < 16; k2++) {                                 \
            {                                                             \
                const float2 v  = *(const float2*)((buf) + 2 * k2);       \
                const float2 w0 = *(const float2*)((W) + (2*k2)   * 64 + c0);\
                const float2 w1 = *(const float2*)((W) + (2*k2+1) * 64 + c0);\
                aA.x = fmaf(v.x, w0.x, fmaf(v.y, w1.x, aA.x));            \
                aA.y = fmaf(v.x, w0.y, fmaf(v.y, w1.y, aA.y));            \
            }                                                             \
            {                                                             \
                const float2 v  = *(const float2*)((buf) + 32 + 2 * k2);  \
                const float2 w0 = *(const float2*)((W) + (32+2*k2)   * 64 + c0);\
                const float2 w1 = *(const float2*)((W) + (32+2*k2+1) * 64 + c0);\
                aB.x = fmaf(v.x, w0.x, fmaf(v.y, w1.x, aB.x));            \
                aB.y = fmaf(v.x, w0.y, fmaf(v.y, w1.y, aB.y));            \
            }                                                             \
        }                                                                 \
        dst.x = aA.x + aB.x;                                              \
        dst.y = aA.y + aB.y;                                              \
    }

__global__ __launch_bounds__(512)
void prep_kernel(const float* __restrict__ x,
                 const float* __restrict__ Wlin, const float* __restrict__ blin,
                 const float* __restrict__ Wu1,  const float* __restrict__ bu1,
                 const float* __restrict__ Wu2,  const float* __restrict__ bu2,
                 const float* __restrict__ Wug1, const float* __restrict__ bug1,
                 const float* __restrict__ Wug2, const float* __restrict__ bug2,
                 const float* __restrict__ Wb1,  const float* __restrict__ bb1,
                 const float* __restrict__ Wbg1, const float* __restrict__ bbg1,
                 const float* __restrict__ Wb2,  const float* __restrict__ Wbg2)
{
    const int tid = threadIdx.x;

    // --- block 128: build bf16 hi/lo W image for main kernel ---
    if (blockIdx.x == 128) {
        for (int idx = tid; idx < 4096; idx += 512) {
            const int k = idx >> 6, c = idx & 63;
            const int off = c * 144 + k * 2;
            {
                const float w = Wb2[idx];
                const __nv_bfloat16 h = __float2bfloat16(w);
                const __nv_bfloat16 l = __float2bfloat16(w - __bfloat162float(h));
                *(__nv_bfloat16*)(g_Wimg + off)        = h;
                *(__nv_bfloat16*)(g_Wimg + 9216 + off) = l;
            }
            {
                const float w = Wbg2[idx];
                const __nv_bfloat16 h = __float2bfloat16(w);
                const __nv_bfloat16 l = __float2bfloat16(w - __bfloat162float(h));
                *(__nv_bfloat16*)(g_Wimg + 18432 + off) = h;
                *(__nv_bfloat16*)(g_Wimg + 27648 + off) = l;
            }
        }
        return;
    }

    extern __shared__ float sm[];
    float* sWlin  = sm;
    float* sWu1   = sm + 4096;
    float* sWu2   = sm + 2 * 4096;
    float* sWug1  = sm + 3 * 4096;
    float* sWug2  = sm + 4 * 4096;
    float* sWb1a  = sm + 5 * 4096;
    float* sWb1b  = sm + 6 * 4096;
    float* sWbg1a = sm + 7 * 4096;
    float* sWbg1b = sm + 8 * 4096;
    float* bufs   = sm + 9 * 4096;   // [16 warps][2][64]

    for (int i = tid; i < 4096; i += 512) {
        sWlin[i]  = Wlin[i];
        sWu1[i]   = Wu1[i];
        sWu2[i]   = Wu2[i];
        sWug1[i]  = Wug1[i];
        sWug2[i]  = Wug2[i];
        sWb1a[i]  = Wb1[i];
        sWb1b[i]  = Wb1[4096 + i];
        sWbg1a[i] = Wbg1[i];
        sWbg1b[i] = Wbg1[4096 + i];
    }
    __syncthreads();   // the only block barrier

    const int w    = tid >> 5;
    const int lane = tid & 31;
    const int c0   = 2 * lane;
    float* buf0 = bufs + w * 128;
    float* buf1 = buf0 + 64;

    const float2 blin2 = *(const float2*)(blin + c0);
    const float2 bu12  = *(const float2*)(bu1  + c0);
    const float2 bu22  = *(const float2*)(bu2  + c0);
    const float2 bug12 = *(const float2*)(bug1 + c0);
    const float2 bug22 = *(const float2*)(bug2 + c0);
    const float2 bb12  = *(const float2*)(bb1  + c0);
    const float2 bbg12 = *(const float2*)(bbg1 + c0);

    for (int r = 0; r < 4; r++) {
        const int row = blockIdx.x * 64 + w * 4 + r;

        *(float2*)(buf0 + c0) = *(const float2*)(x + row * 64 + c0);
        __syncwarp();

        float2 h;  GEMV2(h, buf0, sWlin, blin2);
        __syncwarp();
        *(float2*)(buf1 + c0) = h;
        __syncwarp();

        float2 a1; GEMV2(a1, buf1, sWu1, bu12);
        a1.x = fast_tanh(a1.x); a1.y = fast_tanh(a1.y);
        __syncwarp();
        *(float2*)(buf0 + c0) = a1;
        __syncwarp();

        float2 um; GEMV2(um, buf0, sWu2, bu22);

        float2 a2; GEMV2(a2, buf1, sWug1, bug12);
        a2.x = fast_tanh(a2.x); a2.y = fast_tanh(a2.y);
        __syncwarp();
        *(float2*)(buf0 + c0) = a2;
        __syncwarp();

        float2 ug; GEMV2(ug, buf0, sWug2, bug22);
        float2 U;
        U.x = um.x * fast_sigmoid(ug.x);
        U.y = um.y * fast_sigmoid(ug.y);
        *(float2*)(g_U + row * 64 + c0) = U;

        // binary first-layer factors (4 GEMVs over buf1; 8 indep chains)
        float2 fa = bb12, fb = make_float2(0.f, 0.f);
        float2 fag = bbg12, fbg = make_float2(0.f, 0.f);
        #pragma unroll 8
        for (int k2 = 0; k2 < 32; k2++) {
            const float2 v = *(const float2*)(buf1 + 2 * k2);
            const int r0 = (2 * k2) * 64 + c0, r1 = (2 * k2 + 1) * 64 + c0;
            const float2 wa0 = *(const float2*)(sWb1a  + r0);
            const float2 wa1 = *(const float2*)(sWb1a  + r1);
            const float2 wb0 = *(const float2*)(sWb1b  + r0);
            const float2 wb1 = *(const float2*)(sWb1b  + r1);
            const float2 wc0 = *(const float2*)(sWbg1a + r0);
            const float2 wc1 = *(const float2*)(sWbg1a + r1);
            const float2 wd0 = *(const float2*)(sWbg1b + r0);
            const float2 wd1 = *(const float2*)(sWbg1b + r1);
            fa.x  = fmaf(v.x, wa0.x, fmaf(v.y, wa1.x, fa.x));
            fa.y  = fmaf(v.x, wa0.y, fmaf(v.y, wa1.y, fa.y));
            fb.x  = fmaf(v.x, wb0.x, fmaf(v.y, wb1.x, fb.x));
            fb.y  = fmaf(v.x, wb0.y, fmaf(v.y, wb1.y, fb.y));
            fag.x = fmaf(v.x, wc0.x, fmaf(v.y, wc1.x, fag.x));
            fag.y = fmaf(v.x, wc0.y, fmaf(v.y, wc1.y, fag.y));
            fbg.x = fmaf(v.x, wd0.x, fmaf(v.y, wd1.x, fbg.x));
            fbg.y = fmaf(v.x, wd0.y, fmaf(v.y, wd1.y, fbg.y));
        }
        *(float2*)(g_A  + row * 64 + c0) = fa;
        *(float2*)(g_B  + row * 64 + c0) = fb;
        *(float2*)(g_Ag + row * 64 + c0) = fag;
        *(float2*)(g_Bg + row * 64 + c0) = fbg;
        __syncwarp();
    }
}

// ---------------------------------------------------------------------------
// Kernel 2: one block per (n, 4 j's) = 2 tiles of 2 j's. 2048 blocks.
// Per tile: A[m][k] = tanh(A_j(m)[k] + B_i(m)[k]), m = jj*64+i (M=128,K=64).
// Warp tiles 32m x 32n (4 m-strips x 2 n-halves), BOTH paths per warp,
// 3-pass bf16 hi/lo split; gate in registers; shfl-reduce 32 i-rows.
// ---------------------------------------------------------------------------
#define WPITCH_B  144
#define OFF_WB_HI 0
#define OFF_WB_LO 9216
#define OFF_WG_HI 18432
#define OFF_WG_LO 27648
#define OFF_AB_HI 36864
#define OFF_AB_LO 55296
#define OFF_AG_HI 73728
#define OFF_AG_LO 92160
#define OFF_BB2   110592
#define OFF_BBG2  110848
#define OFF_PART  111104                   // [8][32] floats = 1024 B
#define MAIN_SMEM_BYTES 112128

__global__ __launch_bounds__(256, 2)
void main_kernel(const float* __restrict__ bb2, const float* __restrict__ bbg2,
                 float* __restrict__ out)
{
    extern __shared__ char smem[];
    const uint32_t sb = smem_to_u32(smem);
    const int tid  = threadIdx.x;
    const int wid  = tid >> 5;
    const int lane = tid & 31;
    const int gid  = lane >> 2;
    const int tig  = lane & 3;
    const int n    = blockIdx.x >> 4;
    const int jg   = blockIdx.x & 15;

    // --- one-time: copy precomputed W image (both paths, hi+lo) ---
    {
        const uint4* wsrc = (const uint4*)g_Wimg;
        uint4* wdst = (uint4*)smem;
        #pragma unroll
        for (int i = 0; i < 9; i++)
            wdst[tid + 256 * i] = wsrc[tid + 256 * i];
    }
    float* sbb2  = (float*)(smem + OFF_BB2);
    float* sbbg2 = (float*)(smem + OFF_BBG2);
    if (tid < 64) { sbb2[tid] = bb2[tid]; sbbg2[tid] = bbg2[tid]; }
    __syncthreads();

    // phase-1 mapping: (row, part); coalesced 16B-per-thread loads
    const int row1  = tid >> 1;              // 0..127
    const int part1 = tid & 1;
    const int jj1   = row1 >> 6;
    const int i1    = row1 & 63;
    const int swz1  = ((row1 >> 3) & 1) * 4; // chunk xor

    // MMA mapping: 32m x 32n warp tiles
    const int ms    = wid & 3;               // m-strip
    const int nh    = wid >> 2;              // n-half
    const int m0    = 32 * ms;
    const int cb    = 32 * nh;
    const int arow0 = m0 + (lane & 15);
    const int lsw   = ((lane >> 3) & 1) * 4;
    const int lch   = lane >> 4;

    float* partS = (float*)(smem + OFF_PART);

    for (int t = 0; t < 2; t++) {
        const int j0 = jg * 4 + 2 * t;

        // ---- phase 1: build bf16 hi/lo A tiles (both paths) ----
        #pragma unroll
        for (int p = 0; p < 2; p++) {
            const float* Bbase = (p ? g_Bg : g_B) + (n * 64 + i1) * 64;
            const float* Abase = (p ? g_Ag : g_A) + (n * 64 + j0 + jj1) * 64;
            char* hiB = smem + (p ? OFF_AG_HI : OFF_AB_HI) + row1 * WPITCH_B;
            char* loB = hiB + 18432;
            #pragma unroll
            for (int q = 0; q < 8; q++) {
                const int k0 = q * 8 + part1 * 4;
                const float4 b = *(const float4*)(Bbase + k0);
                const float4 a = *(const float4*)(Abase + k0);
                const float t0 = fast_tanh(a.x + b.x);
                const float t1 = fast_tanh(a.y + b.y);
                const float t2 = fast_tanh(a.z + b.z);
                const float t3 = fast_tanh(a.w + b.w);
                const uint32_t h0 = pack_bf16x2(t0, t1);
                const uint32_t h1 = pack_bf16x2(t2, t3);
                const float hf0 = __uint_as_float(h0 << 16);
                const float hf1 = __uint_as_float(h0 & 0xFFFF0000u);
                const float hf2 = __uint_as_float(h1 << 16);
                const float hf3 = __uint_as_float(h1 & 0xFFFF0000u);
                const uint32_t l0 = pack_bf16x2(t0 - hf0, t1 - hf1);
                const uint32_t l1 = pack_bf16x2(t2 - hf2, t3 - hf3);
                const int boff = ((q ^ swz1) * 16) + part1 * 8;
                *(uint2*)(hiB + boff) = make_uint2(h0, h1);
                *(uint2*)(loB + boff) = make_uint2(l0, l1);
            }
        }
        __syncthreads();   // sync #1

        // ---- MMA: 32x32 warp tile, both paths, 3-pass split ----
        float accb[2][4][4], accg[2][4][4];
        #pragma unroll
        for (int s = 0; s < 2; s++)
            #pragma unroll
            for (int nt = 0; nt < 4; nt++)
                #pragma unroll
                for (int r = 0; r < 4; r++) { accb[s][nt][r] = 0.f; accg[s][nt][r] = 0.f; }

        #pragma unroll
        for (int ks = 0; ks < 4; ks++) {
            const uint32_t chunk = (uint32_t)(((ks * 2 + lch) ^ lsw) * 16);
            uint32_t ah0[4], al0[4], ah1[4], al1[4];
            // ---- path b ----
            {
                const uint32_t ad0 = sb + OFF_AB_HI + (uint32_t)(arow0 * WPITCH_B) + chunk;
                const uint32_t ad1 = ad0 + 16 * WPITCH_B;
                ldm_x4(ah0, ad0);
                ldm_x4(al0, ad0 + 18432);
                ldm_x4(ah1, ad1);
                ldm_x4(al1, ad1 + 18432);
                #pragma unroll
                for (int nt = 0; nt < 4; nt++) {
                    const char* wp = (const char*)smem + OFF_WB_HI +
                        (cb + nt * 8 + gid) * WPITCH_B + ks * 32 + 4 * tig;
                    const uint32_t h0 = *(const uint32_t*)(wp);
                    const uint32_t h1 = *(const uint32_t*)(wp + 16);
                    const uint32_t l0 = *(const uint32_t*)(wp + 9216);
                    const uint32_t l1 = *(const uint32_t*)(wp + 9216 + 16);
                    mma16816(accb[0][nt], ah0, h0, h1);
                    mma16816(accb[0][nt], ah0, l0, l1);
                    mma16816(accb[0][nt], al0, h0, h1);
                    mma16816(accb[1][nt], ah1, h0, h1);
                    mma16816(accb[1][nt], ah1, l0, l1);
                    mma16816(accb[1][nt], al1, h0, h1);
                }
            }
            // ---- path g (reuse fragment registers) ----
            {
                const uint32_t ad0 = sb + OFF_AG_HI + (uint32_t)(arow0 * WPITCH_B) + chunk;
                const uint32_t ad1 = ad0 + 16 * WPITCH_B;
                ldm_x4(ah0, ad0);
                ldm_x4(al0, ad0 + 18432);
                ldm_x4(ah1, ad1);
                ldm_x4(al1, ad1 + 18432);
                #pragma unroll
                for (int nt = 0; nt < 4; nt++) {
                    const char* wp = (const char*)smem + OFF_WG_HI +
                        (cb + nt * 8 + gid) * WPITCH_B + ks * 32 + 4 * tig;
                    const uint32_t h0 = *(const uint32_t*)(wp);
                    const uint32_t h1 = *(const uint32_t*)(wp + 16);
                    const uint32_t l0 = *(const uint32_t*)(wp + 9216);
                    const uint32_t l1 = *(const uint32_t*)(wp + 9216 + 16);
                    mma16816(accg[0][nt], ah0, h0, h1);
                    mma16816(accg[0][nt], ah0, l0, l1);
                    mma16816(accg[0][nt], al0, h0, h1);
                    mma16816(accg[1][nt], ah1, h0, h1);
                    mma16816(accg[1][nt], ah1, l0, l1);
                    mma16816(accg[1][nt], al1, h0, h1);
                }
            }
        }

        // ---- epilogue in registers: bias + gate + 32-row reduce ----
        #pragma unroll
        for (int nt = 0; nt < 4; nt++) {
            const int c0 = cb + nt * 8 + 2 * tig;
            const float2 bb = *(const float2*)(sbb2 + c0);
            const float2 gb = *(const float2*)(sbbg2 + c0);
            float p0 = 0.f, p1 = 0.f;
            #pragma unroll
            for (int s = 0; s < 2; s++) {
                p0 += (accb[s][nt][0] + bb.x) * fast_sigmoid(accg[s][nt][0] + gb.x)
                    + (accb[s][nt][2] + bb.x) * fast_sigmoid(accg[s][nt][2] + gb.x);
                p1 += (accb[s][nt][1] + bb.y) * fast_sigmoid(accg[s][nt][1] + gb.y)
                    + (accb[s][nt][3] + bb.y) * fast_sigmoid(accg[s][nt][3] + gb.y);
            }
            p0 += __shfl_xor_sync(0xFFFFFFFFu, p0, 4);
            p1 += __shfl_xor_sync(0xFFFFFFFFu, p1, 4);
            p0 += __shfl_xor_sync(0xFFFFFFFFu, p0, 8);
            p1 += __shfl_xor_sync(0xFFFFFFFFu, p1, 8);
            p0 += __shfl_xor_sync(0xFFFFFFFFu, p0, 16);
            p1 += __shfl_xor_sync(0xFFFFFFFFu, p1, 16);
            if (lane < 4)   // lanes 0..3: gid=0, tig=lane
                *(float2*)(partS + wid * 32 + nt * 8 + 2 * lane) = make_float2(p0, p1);
        }
        __syncthreads();   // sync #2

        // ---- finalize: sum 2 warp-partials per (jj,c), add U, store ----
        if (tid < 128) {
            const int jj = tid >> 6;
            const int c  = tid & 63;
            const int w1 = (c >> 5) * 4 + 2 * jj;   // ms = 2jj, nh = c>>5
            const int cl = c & 31;
            const float sum = partS[w1 * 32 + cl] + partS[(w1 + 1) * 32 + cl];
            const int o = (n * 64 + j0 + jj) * 64 + c;
            out[o] = g_U[o] + sum * (1.0f / 63.0f);
        }
        // no extra sync: partS(t+1) writes occur only after sync #1 of t+1,
        // which all finalize threads must reach first.
    }
}

// ---------------------------------------------------------------------------
// launch
// ---------------------------------------------------------------------------
extern "C" void kernel_launch(void* const* d_in, const int* in_sizes, int n_in,
                              void* d_out, int out_size)
{
    const float* x    = (const float*)d_in[0];
    const float* Wlin = (const float*)d_in[1];
    const float* blin = (const float*)d_in[2];
    const float* Wu1  = (const float*)d_in[3];
    const float* bu1  = (const float*)d_in[4];
    const float* Wu2  = (const float*)d_in[5];
    const float* bu2  = (const float*)d_in[6];
    const float* Wug1 = (const float*)d_in[7];
    const float* bug1 = (const float*)d_in[8];
    const float* Wug2 = (const float*)d_in[9];
    const float* bug2 = (const float*)d_in[10];
    const float* Wb1  = (const float*)d_in[11];
    const float* bb1  = (const float*)d_in[12];
    const float* Wb2  = (const float*)d_in[13];
    const float* bb2  = (const float*)d_in[14];
    const float* Wbg1 = (const float*)d_in[15];
    const float* bbg1 = (const float*)d_in[16];
    const float* Wbg2 = (const float*)d_in[17];
    const float* bbg2 = (const float*)d_in[18];

    float* out = (float*)d_out;

    const int prep_smem = PREP_SMEM_FLOATS * (int)sizeof(float);   // 155648 B
    cudaFuncSetAttribute(prep_kernel, cudaFuncAttributeMaxDynamicSharedMemorySize, prep_smem);
    cudaFuncSetAttribute(main_kernel, cudaFuncAttributeMaxDynamicSharedMemorySize, MAIN_SMEM_BYTES);

    prep_kernel<<<129, 512, prep_smem>>>(x, Wlin, blin, Wu1, bu1, Wu2, bu2,
                                         Wug1, bug1, Wug2, bug2,
                                         Wb1, bb1, Wbg1, bbg1, Wb2, Wbg2);
    main_kernel<<<2048, 256, MAIN_SMEM_BYTES>>>(bb2, bbg2, out);
}

// round 9
// speedup vs baseline: 3.1757x; 1.5384x over previous
#include <cuda_runtime.h>
#include <cuda_bf16.h>
#include <math.h>
#include <cstdint>

// Problem constants
#define N_ 128
#define K_ 64
#define C_ 64
#define ROWS_ (N_ * K_)   // 8192

// Scratch (device globals: no allocation allowed)
__device__ float g_U [ROWS_ * C_];   // um * ug
__device__ float g_A [ROWS_ * C_];   // h @ Wb1[:C]  + bb1
__device__ float g_B [ROWS_ * C_];   // h @ Wb1[C:]
__device__ float g_Ag[ROWS_ * C_];   // h @ Wbg1[:C] + bbg1
__device__ float g_Bg[ROWS_ * C_];   // h @ Wbg1[C:]
// Precomputed bf16 hi/lo W image in exact main-kernel smem layout:
// [0,9216) Wb hi | [9216,18432) Wb lo | [18432,27648) Wg hi | [27648,36864) Wg lo
__device__ unsigned char g_Wimg[36864];

__device__ __forceinline__ float tanh_fast(float x) {
    float y;
    asm("tanh.approx.f32 %0, %1;" : "=f"(y) : "f"(x));
    return y;
}
__device__ __forceinline__ float fast_sigmoid(float x) {
    return __fdividef(1.0f, 1.0f + __expf(-x));
}

// pack two fp32 into bf16x2 (first arg -> low 16 bits)
__device__ __forceinline__ uint32_t pack_bf16x2(float lo, float hi) {
    uint32_t r;
    asm("cvt.rn.bf16x2.f32 %0, %1, %2;" : "=r"(r) : "f"(hi), "f"(lo));
    return r;
}

__device__ __forceinline__ uint32_t smem_to_u32(const void* p) {
    uint32_t a;
    asm("{ .reg .u64 t; cvta.to.shared.u64 t, %1; cvt.u32.u64 %0, t; }"
        : "=r"(a) : "l"(p));
    return a;
}

// warp-level bf16 HMMA, m16n8k16, row.col, f32 accumulate (base-target PTX)
__device__ __forceinline__ void mma16816(float acc[4], const uint32_t a[4],
                                         uint32_t b0, uint32_t b1) {
    asm volatile(
        "mma.sync.aligned.m16n8k16.row.col.f32.bf16.bf16.f32 "
        "{%0,%1,%2,%3}, {%4,%5,%6,%7}, {%8,%9}, {%0,%1,%2,%3};"
        : "+f"(acc[0]), "+f"(acc[1]), "+f"(acc[2]), "+f"(acc[3])
        : "r"(a[0]), "r"(a[1]), "r"(a[2]), "r"(a[3]), "r"(b0), "r"(b1));
}

__device__ __forceinline__ void ldm_x4(uint32_t r[4], uint32_t addr) {
    asm volatile(
        "ldmatrix.sync.aligned.m8n8.x4.shared.b16 {%0,%1,%2,%3}, [%4];"
        : "=r"(r[0]), "=r"(r[1]), "=r"(r[2]), "=r"(r[3]) : "r"(addr));
}

// ---------------------------------------------------------------------------
// Kernel 1: blocks 0..127, 16 warps x 4 rows, each warp processes its 4 rows
// JOINTLY (batched GEMV: W loads shared across the 4 rows). Warp-autonomous:
// only __syncwarp inside. Block 128 builds the bf16 W image.
// ---------------------------------------------------------------------------
#define PREP_SMEM_FLOATS (9 * 4096 + 16 * 512)

#define GEMV4(ACC, BUF, W, BIAS)                                              \
    {                                                                         \
        ACC[0] = BIAS; ACC[1] = BIAS; ACC[2] = BIAS; ACC[3] = BIAS;           \
        _Pragma("unroll 8")                                                   \
        for (int k2 = 0; k2 < 32; k2++) {                                     \
            const float2 w0 = *(const float2*)((W) + (2 * k2)     * 64 + c0); \
            const float2 w1 = *(const float2*)((W) + (2 * k2 + 1) * 64 + c0); \
            _Pragma("unroll")                                                 \
            for (int r4 = 0; r4 < 4; r4++) {                                  \
                const float2 v = *(const float2*)((BUF) + r4 * 64 + 2 * k2);  \
                ACC[r4].x = fmaf(v.x, w0.x, fmaf(v.y, w1.x, ACC[r4].x));      \
                ACC[r4].y = fmaf(v.x, w0.y, fmaf(v.y, w1.y, ACC[r4].y));      \
            }                                                                 \
        }                                                                     \
    }

__global__ __launch_bounds__(512)
void prep_kernel(const float* __restrict__ x,
                 const float* __restrict__ Wlin, const float* __restrict__ blin,
                 const float* __restrict__ Wu1,  const float* __restrict__ bu1,
                 const float* __restrict__ Wu2,  const float* __restrict__ bu2,
                 const float* __restrict__ Wug1, const float* __restrict__ bug1,
                 const float* __restrict__ Wug2, const float* __restrict__ bug2,
                 const float* __restrict__ Wb1,  const float* __restrict__ bb1,
                 const float* __restrict__ Wbg1, const float* __restrict__ bbg1,
                 const float* __restrict__ Wb2,  const float* __restrict__ Wbg2)
{
    const int tid = threadIdx.x;

    // --- block 128: build bf16 hi/lo W image for main kernel ---
    if (blockIdx.x == 128) {
        for (int idx = tid; idx < 4096; idx += 512) {
            const int k = idx >> 6, c = idx & 63;
            const int off = c * 144 + k * 2;
            {
                const float w = Wb2[idx];
                const __nv_bfloat16 h = __float2bfloat16(w);
                const __nv_bfloat16 l = __float2bfloat16(w - __bfloat162float(h));
                *(__nv_bfloat16*)(g_Wimg + off)        = h;
                *(__nv_bfloat16*)(g_Wimg + 9216 + off) = l;
            }
            {
                const float w = Wbg2[idx];
                const __nv_bfloat16 h = __float2bfloat16(w);
                const __nv_bfloat16 l = __float2bfloat16(w - __bfloat162float(h));
                *(__nv_bfloat16*)(g_Wimg + 18432 + off) = h;
                *(__nv_bfloat16*)(g_Wimg + 27648 + off) = l;
            }
        }
        return;
    }

    extern __shared__ float sm[];
    float* sWlin  = sm;
    float* sWu1   = sm + 4096;
    float* sWu2   = sm + 2 * 4096;
    float* sWug1  = sm + 3 * 4096;
    float* sWug2  = sm + 4 * 4096;
    float* sWb1a  = sm + 5 * 4096;
    float* sWb1b  = sm + 6 * 4096;
    float* sWbg1a = sm + 7 * 4096;
    float* sWbg1b = sm + 8 * 4096;
    float* bufs   = sm + 9 * 4096;   // [16 warps][2][4][64]

    for (int i = tid; i < 4096; i += 512) {
        sWlin[i]  = Wlin[i];
        sWu1[i]   = Wu1[i];
        sWu2[i]   = Wu2[i];
        sWug1[i]  = Wug1[i];
        sWug2[i]  = Wug2[i];
        sWb1a[i]  = Wb1[i];
        sWb1b[i]  = Wb1[4096 + i];
        sWbg1a[i] = Wbg1[i];
        sWbg1b[i] = Wbg1[4096 + i];
    }
    __syncthreads();   // the only block barrier

    const int w    = tid >> 5;
    const int lane = tid & 31;
    const int c0   = 2 * lane;
    float* buf0 = bufs + w * 512;
    float* buf1 = buf0 + 256;
    const int row0 = blockIdx.x * 64 + w * 4;

    const float2 blin2 = *(const float2*)(blin + c0);
    const float2 bu12  = *(const float2*)(bu1  + c0);
    const float2 bu22  = *(const float2*)(bu2  + c0);
    const float2 bug12 = *(const float2*)(bug1 + c0);
    const float2 bug22 = *(const float2*)(bug2 + c0);
    const float2 bb12  = *(const float2*)(bb1  + c0);
    const float2 bbg12 = *(const float2*)(bbg1 + c0);
    const float2 zero2 = make_float2(0.f, 0.f);

    // stage 1: x rows -> buf0
    #pragma unroll
    for (int r = 0; r < 4; r++)
        *(float2*)(buf0 + r * 64 + c0) = *(const float2*)(x + (row0 + r) * 64 + c0);
    __syncwarp();

    // stage 2: h = x @ Wlin + blin -> buf1
    float2 hh[4]; GEMV4(hh, buf0, sWlin, blin2);
    __syncwarp();
    #pragma unroll
    for (int r = 0; r < 4; r++) *(float2*)(buf1 + r * 64 + c0) = hh[r];
    __syncwarp();

    // stage 3: t1 = tanh(h @ Wu1 + bu1) -> buf0
    float2 tt[4]; GEMV4(tt, buf1, sWu1, bu12);
    #pragma unroll
    for (int r = 0; r < 4; r++) {
        tt[r].x = tanh_fast(tt[r].x); tt[r].y = tanh_fast(tt[r].y);
    }
    __syncwarp();
    #pragma unroll
    for (int r = 0; r < 4; r++) *(float2*)(buf0 + r * 64 + c0) = tt[r];
    __syncwarp();

    // stage 4: um = t1 @ Wu2 + bu2 (registers)
    float2 um[4]; GEMV4(um, buf0, sWu2, bu22);

    // stage 5: t2 = tanh(h @ Wug1 + bug1) -> buf0
    float2 t2[4]; GEMV4(t2, buf1, sWug1, bug12);
    #pragma unroll
    for (int r = 0; r < 4; r++) {
        t2[r].x = tanh_fast(t2[r].x); t2[r].y = tanh_fast(t2[r].y);
    }
    __syncwarp();   // stage-4 buf0 reads complete in all lanes
    #pragma unroll
    for (int r = 0; r < 4; r++) *(float2*)(buf0 + r * 64 + c0) = t2[r];
    __syncwarp();

    // stage 6: ug = sigmoid(t2 @ Wug2 + bug2); U = um * ug
    float2 ug[4]; GEMV4(ug, buf0, sWug2, bug22);
    #pragma unroll
    for (int r = 0; r < 4; r++) {
        float2 U;
        U.x = um[r].x * fast_sigmoid(ug[r].x);
        U.y = um[r].y * fast_sigmoid(ug[r].y);
        *(float2*)(g_U + (row0 + r) * 64 + c0) = U;
    }

    // stage 7: binary first-layer factors (4 matrices x 4 rows, shared W loads)
    float2 fa[4], fb[4], fag[4], fbg[4];
    #pragma unroll
    for (int r = 0; r < 4; r++) { fa[r] = bb12; fb[r] = zero2; fag[r] = bbg12; fbg[r] = zero2; }
    #pragma unroll 4
    for (int k2 = 0; k2 < 32; k2++) {
        const int r0 = (2 * k2) * 64 + c0, r1 = (2 * k2 + 1) * 64 + c0;
        const float2 wa0 = *(const float2*)(sWb1a  + r0);
        const float2 wa1 = *(const float2*)(sWb1a  + r1);
        const float2 wb0 = *(const float2*)(sWb1b  + r0);
        const float2 wb1 = *(const float2*)(sWb1b  + r1);
        const float2 wc0 = *(const float2*)(sWbg1a + r0);
        const float2 wc1 = *(const float2*)(sWbg1a + r1);
        const float2 wd0 = *(const float2*)(sWbg1b + r0);
        const float2 wd1 = *(const float2*)(sWbg1b + r1);
        #pragma unroll
        for (int r = 0; r < 4; r++) {
            const float2 v = *(const float2*)(buf1 + r * 64 + 2 * k2);
            fa[r].x  = fmaf(v.x, wa0.x, fmaf(v.y, wa1.x, fa[r].x));
            fa[r].y  = fmaf(v.x, wa0.y, fmaf(v.y, wa1.y, fa[r].y));
            fb[r].x  = fmaf(v.x, wb0.x, fmaf(v.y, wb1.x, fb[r].x));
            fb[r].y  = fmaf(v.x, wb0.y, fmaf(v.y, wb1.y, fb[r].y));
            fag[r].x = fmaf(v.x, wc0.x, fmaf(v.y, wc1.x, fag[r].x));
            fag[r].y = fmaf(v.x, wc0.y, fmaf(v.y, wc1.y, fag[r].y));
            fbg[r].x = fmaf(v.x, wd0.x, fmaf(v.y, wd1.x, fbg[r].x));
            fbg[r].y = fmaf(v.x, wd0.y, fmaf(v.y, wd1.y, fbg[r].y));
        }
    }
    #pragma unroll
    for (int r = 0; r < 4; r++) {
        *(float2*)(g_A  + (row0 + r) * 64 + c0) = fa[r];
        *(float2*)(g_B  + (row0 + r) * 64 + c0) = fb[r];
        *(float2*)(g_Ag + (row0 + r) * 64 + c0) = fag[r];
        *(float2*)(g_Bg + (row0 + r) * 64 + c0) = fbg[r];
    }
}

// ---------------------------------------------------------------------------
// Kernel 2: one block per (n, 4 j's) = 2 tiles of 2 j's. 2048 blocks.
// Per tile: A[m][k] = tanh(A_j(m)[k] + B_i(m)[k]), m = jj*64+i (M=128,K=64).
// Phase 1 now fully coalesced: warp loads 2 consecutive B rows (contiguous
// 512B), A_j rows held in registers, each B float4 reused for both jj.
// Warp tiles 32m x 32n, both paths, 3-pass bf16 hi/lo split; gate in regs.
// ---------------------------------------------------------------------------
#define WPITCH_B  144
#define OFF_WB_HI 0
#define OFF_WB_LO 9216
#define OFF_WG_HI 18432
#define OFF_WG_LO 27648
#define OFF_AB_HI 36864
#define OFF_AB_LO 55296
#define OFF_AG_HI 73728
#define OFF_AG_LO 92160
#define OFF_BB2   110592
#define OFF_BBG2  110848
#define OFF_PART  111104                   // [8][32] floats = 1024 B
#define MAIN_SMEM_BYTES 112128

__global__ __launch_bounds__(256, 2)
void main_kernel(const float* __restrict__ bb2, const float* __restrict__ bbg2,
                 float* __restrict__ out)
{
    extern __shared__ char smem[];
    const uint32_t sb = smem_to_u32(smem);
    const int tid  = threadIdx.x;
    const int wid  = tid >> 5;
    const int lane = tid & 31;
    const int gid  = lane >> 2;
    const int tig  = lane & 3;
    const int n    = blockIdx.x >> 4;
    const int jg   = blockIdx.x & 15;

    // --- one-time: copy precomputed W image (both paths, hi+lo) ---
    {
        const uint4* wsrc = (const uint4*)g_Wimg;
        uint4* wdst = (uint4*)smem;
        #pragma unroll
        for (int i = 0; i < 9; i++)
            wdst[tid + 256 * i] = wsrc[tid + 256 * i];
    }
    float* sbb2  = (float*)(smem + OFF_BB2);
    float* sbbg2 = (float*)(smem + OFF_BBG2);
    if (tid < 64) { sbb2[tid] = bb2[tid]; sbbg2[tid] = bbg2[tid]; }
    __syncthreads();

    // phase-1 mapping: (rbase, ch) — coalesced full-row loads
    const int rbase = tid >> 4;              // 0..15
    const int ch    = tid & 15;              // float4-chunk within row
    const int q1    = ch >> 1;               // 16B chunk index 0..7
    const int part1 = ch & 1;                // 8B half
    const int swz1  = ((rbase >> 3) & 1) * 4;  // row bit3 == rbase bit3

    // MMA mapping: 32m x 32n warp tiles
    const int ms    = wid & 3;               // m-strip
    const int nh    = wid >> 2;              // n-half
    const int m0    = 32 * ms;
    const int cb    = 32 * nh;
    const int arow0 = m0 + (lane & 15);
    const int lsw   = ((lane >> 3) & 1) * 4;
    const int lch   = lane >> 4;

    float* partS = (float*)(smem + OFF_PART);

    for (int t = 0; t < 2; t++) {
        const int j0 = jg * 4 + 2 * t;

        // ---- phase 1: build bf16 hi/lo A tiles (both paths), coalesced ----
        #pragma unroll
        for (int p = 0; p < 2; p++) {
            const float* Bsrc = (p ? g_Bg : g_B) + n * 4096;
            const float* Asrc = (p ? g_Ag : g_A) + (n * 64 + j0) * 64 + 4 * ch;
            char* hiB = smem + (p ? OFF_AG_HI : OFF_AB_HI);
            char* loB = hiB + 18432;
            const float4 a0 = *(const float4*)(Asrc);
            const float4 a1 = *(const float4*)(Asrc + 64);
            #pragma unroll
            for (int c = 0; c < 4; c++) {
                const int i = 16 * c + rbase;
                const float4 b = *(const float4*)(Bsrc + i * 64 + 4 * ch);
                #pragma unroll
                for (int jj = 0; jj < 2; jj++) {
                    const float4 a = jj ? a1 : a0;
                    const int row = jj * 64 + i;
                    const float t0 = tanh_fast(a.x + b.x);
                    const float t1 = tanh_fast(a.y + b.y);
                    const float t2 = tanh_fast(a.z + b.z);
                    const float t3 = tanh_fast(a.w + b.w);
                    const uint32_t h0 = pack_bf16x2(t0, t1);
                    const uint32_t h1 = pack_bf16x2(t2, t3);
                    const float hf0 = __uint_as_float(h0 << 16);
                    const float hf1 = __uint_as_float(h0 & 0xFFFF0000u);
                    const float hf2 = __uint_as_float(h1 << 16);
                    const float hf3 = __uint_as_float(h1 & 0xFFFF0000u);
                    const uint32_t l0 = pack_bf16x2(t0 - hf0, t1 - hf1);
                    const uint32_t l1 = pack_bf16x2(t2 - hf2, t3 - hf3);
                    const int boff = row * WPITCH_B + ((q1 ^ swz1) * 16) + part1 * 8;
                    *(uint2*)(hiB + boff) = make_uint2(h0, h1);
                    *(uint2*)(loB + boff) = make_uint2(l0, l1);
                }
            }
        }
        __syncthreads();   // sync #1

        // ---- MMA: 32x32 warp tile, both paths, 3-pass split ----
        float accb[2][4][4], accg[2][4][4];
        #pragma unroll
        for (int s = 0; s < 2; s++)
            #pragma unroll
            for (int nt = 0; nt < 4; nt++)
                #pragma unroll
                for (int r = 0; r < 4; r++) { accb[s][nt][r] = 0.f; accg[s][nt][r] = 0.f; }

        #pragma unroll
        for (int ks = 0; ks < 4; ks++) {
            const uint32_t chunk = (uint32_t)(((ks * 2 + lch) ^ lsw) * 16);
            uint32_t ah0[4], al0[4], ah1[4], al1[4];
            // ---- path b ----
            {
                const uint32_t ad0 = sb + OFF_AB_HI + (uint32_t)(arow0 * WPITCH_B) + chunk;
                const uint32_t ad1 = ad0 + 16 * WPITCH_B;
                ldm_x4(ah0, ad0);
                ldm_x4(al0, ad0 + 18432);
                ldm_x4(ah1, ad1);
                ldm_x4(al1, ad1 + 18432);
                #pragma unroll
                for (int nt = 0; nt < 4; nt++) {
                    const char* wp = (const char*)smem + OFF_WB_HI +
                        (cb + nt * 8 + gid) * WPITCH_B + ks * 32 + 4 * tig;
                    const uint32_t h0 = *(const uint32_t*)(wp);
                    const uint32_t h1 = *(const uint32_t*)(wp + 16);
                    const uint32_t l0 = *(const uint32_t*)(wp + 9216);
                    const uint32_t l1 = *(const uint32_t*)(wp + 9216 + 16);
                    mma16816(accb[0][nt], ah0, h0, h1);
                    mma16816(accb[0][nt], ah0, l0, l1);
                    mma16816(accb[0][nt], al0, h0, h1);
                    mma16816(accb[1][nt], ah1, h0, h1);
                    mma16816(accb[1][nt], ah1, l0, l1);
                    mma16816(accb[1][nt], al1, h0, h1);
                }
            }
            // ---- path g (reuse fragment registers) ----
            {
                const uint32_t ad0 = sb + OFF_AG_HI + (uint32_t)(arow0 * WPITCH_B) + chunk;
                const uint32_t ad1 = ad0 + 16 * WPITCH_B;
                ldm_x4(ah0, ad0);
                ldm_x4(al0, ad0 + 18432);
                ldm_x4(ah1, ad1);
                ldm_x4(al1, ad1 + 18432);
                #pragma unroll
                for (int nt = 0; nt < 4; nt++) {
                    const char* wp = (const char*)smem + OFF_WG_HI +
                        (cb + nt * 8 + gid) * WPITCH_B + ks * 32 + 4 * tig;
                    const uint32_t h0 = *(const uint32_t*)(wp);
                    const uint32_t h1 = *(const uint32_t*)(wp + 16);
                    const uint32_t l0 = *(const uint32_t*)(wp + 9216);
                    const uint32_t l1 = *(const uint32_t*)(wp + 9216 + 16);
                    mma16816(accg[0][nt], ah0, h0, h1);
                    mma16816(accg[0][nt], ah0, l0, l1);
                    mma16816(accg[0][nt], al0, h0, h1);
                    mma16816(accg[1][nt], ah1, h0, h1);
                    mma16816(accg[1][nt], ah1, l0, l1);
                    mma16816(accg[1][nt], al1, h0, h1);
                }
            }
        }

        // ---- epilogue in registers: bias + gate + 32-row reduce ----
        #pragma unroll
        for (int nt = 0; nt < 4; nt++) {
            const int c0 = cb + nt * 8 + 2 * tig;
            const float2 bb = *(const float2*)(sbb2 + c0);
            const float2 gb = *(const float2*)(sbbg2 + c0);
            float p0 = 0.f, p1 = 0.f;
            #pragma unroll
            for (int s = 0; s < 2; s++) {
                p0 += (accb[s][nt][0] + bb.x) * fast_sigmoid(accg[s][nt][0] + gb.x)
                    + (accb[s][nt][2] + bb.x) * fast_sigmoid(accg[s][nt][2] + gb.x);
                p1 += (accb[s][nt][1] + bb.y) * fast_sigmoid(accg[s][nt][1] + gb.y)
                    + (accb[s][nt][3] + bb.y) * fast_sigmoid(accg[s][nt][3] + gb.y);
            }
            p0 += __shfl_xor_sync(0xFFFFFFFFu, p0, 4);
            p1 += __shfl_xor_sync(0xFFFFFFFFu, p1, 4);
            p0 += __shfl_xor_sync(0xFFFFFFFFu, p0, 8);
            p1 += __shfl_xor_sync(0xFFFFFFFFu, p1, 8);
            p0 += __shfl_xor_sync(0xFFFFFFFFu, p0, 16);
            p1 += __shfl_xor_sync(0xFFFFFFFFu, p1, 16);
            if (lane < 4)   // lanes 0..3: gid=0, tig=lane
                *(float2*)(partS + wid * 32 + nt * 8 + 2 * lane) = make_float2(p0, p1);
        }
        __syncthreads();   // sync #2

        // ---- finalize: sum 2 warp-partials per (jj,c), add U, store ----
        if (tid < 128) {
            const int jj = tid >> 6;
            const int c  = tid & 63;
            const int w1 = (c >> 5) * 4 + 2 * jj;   // ms = 2jj, nh = c>>5
            const int cl = c & 31;
            const float sum = partS[w1 * 32 + cl] + partS[(w1 + 1) * 32 + cl];
            const int o = (n * 64 + j0 + jj) * 64 + c;
            out[o] = g_U[o] + sum * (1.0f / 63.0f);
        }
        // no extra sync: partS(t+1) writes occur only after sync #1 of t+1,
        // which all finalize threads must reach first.
    }
}

// ---------------------------------------------------------------------------
// launch
// ---------------------------------------------------------------------------
extern "C" void kernel_launch(void* const* d_in, const int* in_sizes, int n_in,
                              void* d_out, int out_size)
{
    const float* x    = (const float*)d_in[0];
    const float* Wlin = (const float*)d_in[1];
    const float* blin = (const float*)d_in[2];
    const float* Wu1  = (const float*)d_in[3];
    const float* bu1  = (const float*)d_in[4];
    const float* Wu2  = (const float*)d_in[5];
    const float* bu2  = (const float*)d_in[6];
    const float* Wug1 = (const float*)d_in[7];
    const float* bug1 = (const float*)d_in[8];
    const float* Wug2 = (const float*)d_in[9];
    const float* bug2 = (const float*)d_in[10];
    const float* Wb1  = (const float*)d_in[11];
    const float* bb1  = (const float*)d_in[12];
    const float* Wb2  = (const float*)d_in[13];
    const float* bb2  = (const float*)d_in[14];
    const float* Wbg1 = (const float*)d_in[15];
    const float* bbg1 = (const float*)d_in[16];
    const float* Wbg2 = (const float*)d_in[17];
    const float* bbg2 = (const float*)d_in[18];

    float* out = (float*)d_out;

    const int prep_smem = PREP_SMEM_FLOATS * (int)sizeof(float);   // 180224 B
    cudaFuncSetAttribute(prep_kernel, cudaFuncAttributeMaxDynamicSharedMemorySize, prep_smem);
    cudaFuncSetAttribute(main_kernel, cudaFuncAttributeMaxDynamicSharedMemorySize, MAIN_SMEM_BYTES);

    prep_kernel<<<129, 512, prep_smem>>>(x, Wlin, blin, Wu1, bu1, Wu2, bu2,
                                         Wug1, bug1, Wug2, bug2,
                                         Wb1, bb1, Wbg1, bbg1, Wb2, Wbg2);
    main_kernel<<<2048, 256, MAIN_SMEM_BYTES>>>(bb2, bbg2, out);
}